// round 1
// baseline (speedup 1.0000x reference)
#include <cuda_runtime.h>
#include <math.h>

#define TT   24
#define BB   64
#define NI   32
#define IL   24
#define VEC  24
#define NS   256
#define HH   256
#define DIN  288   // NI + NS
#define G3   768   // 3 useful gates (i,g,o) * 256
#define LAM  0.2f
#define NTHREADS 1024

// --------- device scratch (no allocation allowed) ----------
__device__ float g_WihT[DIN * G3];   // [k][gg], gg in {i rows, g rows, o rows}
__device__ float g_gbias[G3];

__device__ __forceinline__ float frcp(float x) {
    float y; asm("rcp.approx.f32 %0, %1;" : "=f"(y) : "f"(x)); return y;
}

// ---------- prep: transpose Wih (drop f-gate rows), fold biases ----------
__global__ void prep_kernel(const float* __restrict__ Wih,
                            const float* __restrict__ bih,
                            const float* __restrict__ bhh) {
    int idx = blockIdx.x * blockDim.x + threadIdx.x;
    int total = DIN * G3;
    for (int i = idx; i < total; i += gridDim.x * blockDim.x) {
        int k = i / G3, gg = i - k * G3;
        int r = (gg < 256) ? gg : gg + 256;   // skip f rows [256,512)
        g_WihT[i] = Wih[r * DIN + k];
    }
    if (idx < G3) {
        int r = (idx < 256) ? idx : idx + 256;
        g_gbias[idx] = bih[r] + bhh[r];
    }
}

// smem layout (floats)
#define U_OFF      0          // union: precompute {Wcg 18432 | Gs 8448} -> later {Wll 6144 | Wlg 6144}
#define U_SIZE     26880
#define TXG_OFF    (U_OFF + U_SIZE)      // 6144
#define TXL_OFF    (TXG_OFF + 6144)      // 768
#define GARR_OFF   (TXL_OFF + 768)       // 768
#define XV_OFF     (GARR_OFF + 768)      // 288
#define CV_OFF     (XV_OFF + 288)        // 256
#define YV_OFF     (CV_OFF + 256)        // 48
#define TVL_OFF    (YV_OFF + 48)         // 48 (float2[24])
#define TVG_OFF    (TVL_OFF + 48)        // 48
#define PSL_OFF    (TVG_OFF + 48)        // 768
#define PSG_OFF    (PSL_OFF + 768)       // 1024
#define SLV_OFF    (PSG_OFF + 1024)      // 32
#define SGV_OFF    (SLV_OFF + 32)        // 256
#define LAV_OFF    (SGV_OFF + 256)       // 32
#define GAV_OFF    (LAV_OFF + 32)        // 256
#define RED_OFF    (GAV_OFF + 256)       // 33
#define SVL_OFF    (RED_OFF + 33)        // 24
#define SVG_OFF    (SVL_OFF + 24)        // 24
#define SBLL_OFF   (SVG_OFF + 24)        // 24
#define SBLG_OFF   (SBLL_OFF + 24)       // 24
#define SMEM_FLOATS (SBLG_OFF + 24)
#define SMEM_BYTES (SMEM_FLOATS * 4)

__global__ __launch_bounds__(NTHREADS, 1)
void spatial_attn_kernel(
    const float* __restrict__ local_inputs,   // [T,B,NI]
    const float* __restrict__ global_inputs,  // [T,B,NS]
    const float* __restrict__ local_states,   // [B,NI,IL]
    const float* __restrict__ global_states,  // [B,NS,NI,IL]
    const float* __restrict__ distmat,        // [B,NS]
    const float* __restrict__ la0,            // [B,NI]
    const float* __restrict__ ga0,            // [B,NS]
    const float* __restrict__ Wcl, const float* __restrict__ bcl,
    const float* __restrict__ Wll, const float* __restrict__ bll,
    const float* __restrict__ vl,
    const float* __restrict__ Wcg, const float* __restrict__ bcg,
    const float* __restrict__ Wlg, const float* __restrict__ blg,
    const float* __restrict__ vg,
    float* __restrict__ out)
{
    extern __shared__ float sm[];
    float* sWcg = sm + U_OFF;            // precompute phase
    float* sGs  = sm + U_OFF + 18432;    // 256*33 padded
    float* sWll = sm + U_OFF;            // steady phase
    float* sWlg = sm + U_OFF + 6144;
    float* TXg  = sm + TXG_OFF;
    float* TXl  = sm + TXL_OFF;
    float* garr = sm + GARR_OFF;
    float* xv   = sm + XV_OFF;
    float* cv   = sm + CV_OFF;
    float* yv   = sm + YV_OFF;
    float2* tvl = (float2*)(sm + TVL_OFF);
    float2* tvg = (float2*)(sm + TVG_OFF);
    float* psl  = sm + PSL_OFF;
    float* psg  = sm + PSG_OFF;
    float* slv  = sm + SLV_OFF;
    float* sgv  = sm + SGV_OFF;
    float* lav  = sm + LAV_OFF;
    float* gav  = sm + GAV_OFF;
    float* red  = sm + RED_OFF;
    float* svl  = sm + SVL_OFF;
    float* svg  = sm + SVG_OFF;
    float* sbll = sm + SBLL_OFF;
    float* sblg = sm + SBLG_OFF;

    const int b = blockIdx.x;
    const int tid = threadIdx.x;

    // ---------- precompute TXl = tanh(hf_l) ----------
    if (tid < G3) {  // 24*32 pairs (o,l)
        int o = tid >> 5, l = tid & 31;
        float acc = __ldg(&bcl[o]);
        const float* ls = local_states + b * (NI * IL);
        #pragma unroll
        for (int c = 0; c < IL; c++)
            acc = fmaf(__ldg(&Wcl[o * IL + c]), __ldg(&ls[c * NI + l]), acc);
        TXl[tid] = tanhf(acc);
    }

    // load Wcg into smem
    for (int i = tid; i < VEC * IL * NI; i += NTHREADS) sWcg[i] = Wcg[i];
    __syncthreads();

    // ---------- precompute TXg = tanh(hf_g), register-tiled GEMM ----------
    {
        int og = tid >> 7;       // 0..7  -> o block of 3
        int s0 = tid & 127;      // 0..127 -> s in {s0, s0+128}
        float a00=0.f,a01=0.f,a10=0.f,a11=0.f,a20=0.f,a21=0.f;
        const float* gsb = global_states + (size_t)b * (NS * NI * IL);
        for (int c = 0; c < IL; c++) {
            __syncthreads();
            for (int i = tid; i < NS * NI; i += NTHREADS) {
                int s = i >> 5, j = i & 31;
                sGs[s * 33 + j] = gsb[c * (NS * NI) + i];
            }
            __syncthreads();
            #pragma unroll 8
            for (int j = 0; j < NI; j++) {
                float gA = sGs[s0 * 33 + j];
                float gB = sGs[(s0 + 128) * 33 + j];
                float w0 = sWcg[((og*3+0) * IL + c) * NI + j];
                float w1 = sWcg[((og*3+1) * IL + c) * NI + j];
                float w2 = sWcg[((og*3+2) * IL + c) * NI + j];
                a00 = fmaf(w0, gA, a00); a01 = fmaf(w0, gB, a01);
                a10 = fmaf(w1, gA, a10); a11 = fmaf(w1, gB, a11);
                a20 = fmaf(w2, gA, a20); a21 = fmaf(w2, gB, a21);
            }
        }
        float b0 = __ldg(&bcg[og*3+0]);
        float b1 = __ldg(&bcg[og*3+1]);
        float b2 = __ldg(&bcg[og*3+2]);
        __syncthreads();
        TXg[(og*3+0)*NS + s0      ] = tanhf(a00 + b0);
        TXg[(og*3+0)*NS + s0 + 128] = tanhf(a01 + b0);
        TXg[(og*3+1)*NS + s0      ] = tanhf(a10 + b1);
        TXg[(og*3+1)*NS + s0 + 128] = tanhf(a11 + b1);
        TXg[(og*3+2)*NS + s0      ] = tanhf(a20 + b2);
        TXg[(og*3+2)*NS + s0 + 128] = tanhf(a21 + b2);
    }
    __syncthreads();

    // ---------- steady-state smem: Wll/Wlg, consts, initial attention ----------
    for (int i = tid; i < VEC * HH; i += NTHREADS) { sWll[i] = Wll[i]; sWlg[i] = Wlg[i]; }
    if (tid < VEC) { svl[tid] = vl[tid]; svg[tid] = vg[tid]; sbll[tid] = bll[tid]; sblg[tid] = blg[tid]; }
    if (tid < NI)  lav[tid] = la0[b * NI + tid];
    if (tid < NS)  gav[tid] = ga0[b * NS + tid];
    __syncthreads();

    float* out_h  = out;                         // [T,B,H]
    float* out_c  = out + TT * BB * HH;          // [B,H]
    float* out_la = out_c + BB * HH;             // [T,B,NI]
    float* out_ga = out_la + TT * BB * NI;       // [T,B,NS]

    const int w = tid >> 5, lane = tid & 31;

    for (int t = 0; t < TT; t++) {
        // x = [la*l_inp, ga*g_inp]
        if (tid < NI)        xv[tid] = lav[tid] * __ldg(&local_inputs[(t * BB + b) * NI + tid]);
        else if (tid < DIN)  xv[tid] = gav[tid - NI] * __ldg(&global_inputs[(t * BB + b) * NS + (tid - NI)]);
        __syncthreads();

        // gates (i,g,o): coalesced stream of WihT
        if (tid < G3) {
            float acc = g_gbias[tid];
            const float* wt = g_WihT + tid;
            #pragma unroll 8
            for (int k = 0; k < DIN; k++)
                acc = fmaf(xv[k], wt[k * G3], acc);
            garr[tid] = acc;
        }
        __syncthreads();

        // LSTM cell (c0=h0=0): c = sig(i)*tanh(g); h = sig(o)*tanh(c)
        if (tid < HH) {
            float ig = garr[tid], gg = garr[256 + tid], og = garr[512 + tid];
            float si = 1.f / (1.f + __expf(-ig));
            float cval = si * tanhf(gg);
            float so = 1.f / (1.f + __expf(-og));
            float hval = so * tanhf(cval);
            cv[tid] = cval;
            out_h[(size_t)(t * BB + b) * HH + tid] = hval;
            if (t == TT - 1) out_c[(size_t)b * HH + tid] = cval;
        }
        __syncthreads();

        // y_l[d], y_g[d]: warp-per-d dot products over c
        if (w < VEC) {
            float a = 0.f, bgn = 0.f;
            const float* wr  = sWll + w * HH;
            const float* wr2 = sWlg + w * HH;
            #pragma unroll
            for (int i = 0; i < HH / 32; i++) {
                float cc = cv[lane + 32 * i];
                a   = fmaf(cc, wr[lane + 32 * i], a);
                bgn = fmaf(cc, wr2[lane + 32 * i], bgn);
            }
            #pragma unroll
            for (int off = 16; off; off >>= 1) {
                a   += __shfl_xor_sync(0xffffffffu, a, off);
                bgn += __shfl_xor_sync(0xffffffffu, bgn, off);
            }
            if (lane == 0) { yv[w] = a + sbll[w]; yv[VEC + w] = bgn + sblg[w]; }
        }
        __syncthreads();
        if (tid < VEC)              tvl[tid]       = make_float2(tanhf(yv[tid]),       svl[tid]);
        else if (tid < 2 * VEC)     tvg[tid - VEC] = make_float2(tanhf(yv[tid]),       svg[tid - VEC]);
        __syncthreads();

        // s_g partials: tanh(x+y) = (TX+TY)/(1+TX*TY), MUFU = 1 rcp per term
        {
            int grp = tid >> 8, s = tid & 255;
            float tx_[6];
            #pragma unroll
            for (int oi = 0; oi < 6; oi++) tx_[oi] = TXg[(grp * 6 + oi) * NS + s];
            float acc = 0.f;
            #pragma unroll 6
            for (int d = 0; d < VEC; d++) {
                float2 p = tvg[d];
                #pragma unroll
                for (int oi = 0; oi < 6; oi++) {
                    float num = tx_[oi] + p.x;
                    float den = fmaf(tx_[oi], p.x, 1.f);
                    acc = fmaf(p.y * num, frcp(den), acc);
                }
            }
            psg[tid] = acc;
        }
        // s_l partials
        if (tid < G3) {
            float tx = TXl[tid];
            float acc = 0.f;
            #pragma unroll
            for (int d = 0; d < VEC; d++) {
                float2 p = tvl[d];
                float num = tx + p.x;
                float den = fmaf(tx, p.x, 1.f);
                acc = fmaf(p.y * num, frcp(den), acc);
            }
            psl[tid] = acc;
        }
        __syncthreads();

        // reduce partials + distmat mixing
        if (tid < NS) {
            float v = psg[tid] + psg[256 + tid] + psg[512 + tid] + psg[768 + tid];
            sgv[tid] = (1.f - LAM) * v + LAM * __ldg(&distmat[b * NS + tid]);
        } else if (tid < NS + NI) {
            int l = tid - NS;
            float a = 0.f;
            #pragma unroll
            for (int o = 0; o < VEC; o++) a += psl[o * NI + l];
            slv[l] = a;
        }
        __syncthreads();

        // softmax over s_g (256) using warps 0..7
        if (tid < NS) {
            float v = sgv[tid];
            float m = v;
            #pragma unroll
            for (int off = 16; off; off >>= 1) m = fmaxf(m, __shfl_xor_sync(0xffffffffu, m, off));
            if (lane == 0) red[w] = m;
        }
        __syncthreads();
        if (tid < NS) {
            float m = fmaxf(fmaxf(fmaxf(red[0], red[1]), fmaxf(red[2], red[3])),
                            fmaxf(fmaxf(red[4], red[5]), fmaxf(red[6], red[7])));
            float e = __expf(sgv[tid] - m);
            sgv[tid] = e;
            float su = e;
            #pragma unroll
            for (int off = 16; off; off >>= 1) su += __shfl_xor_sync(0xffffffffu, su, off);
            if (lane == 0) red[8 + w] = su;
        }
        // softmax over s_l (32) with warp 16
        if (w == 16) {
            float v = slv[lane];
            float m = v;
            #pragma unroll
            for (int off = 16; off; off >>= 1) m = fmaxf(m, __shfl_xor_sync(0xffffffffu, m, off));
            float e = __expf(v - m);
            float su = e;
            #pragma unroll
            for (int off = 16; off; off >>= 1) su += __shfl_xor_sync(0xffffffffu, su, off);
            float a = e / su;
            lav[lane] = a;
            out_la[(size_t)(t * BB + b) * NI + lane] = a;
        }
        __syncthreads();
        if (tid < NS) {
            float su = red[8] + red[9] + red[10] + red[11] + red[12] + red[13] + red[14] + red[15];
            float a = sgv[tid] / su;
            gav[tid] = a;
            out_ga[(size_t)(t * BB + b) * NS + tid] = a;
        }
        __syncthreads();
    }
}

extern "C" void kernel_launch(void* const* d_in, const int* in_sizes, int n_in,
                              void* d_out, int out_size) {
    const float* local_inputs  = (const float*)d_in[0];
    const float* global_inputs = (const float*)d_in[1];
    const float* local_states  = (const float*)d_in[2];
    const float* global_states = (const float*)d_in[3];
    const float* distmat       = (const float*)d_in[4];
    const float* la0           = (const float*)d_in[5];
    const float* ga0           = (const float*)d_in[6];
    const float* Wcl = (const float*)d_in[7];
    const float* bcl = (const float*)d_in[8];
    const float* Wll = (const float*)d_in[9];
    const float* bll = (const float*)d_in[10];
    const float* vl  = (const float*)d_in[11];
    const float* Wcg = (const float*)d_in[12];
    const float* bcg = (const float*)d_in[13];
    const float* Wlg = (const float*)d_in[14];
    const float* blg = (const float*)d_in[15];
    const float* vg  = (const float*)d_in[16];
    const float* Wih = (const float*)d_in[17];
    const float* bih = (const float*)d_in[18];
    const float* bhh = (const float*)d_in[19];
    float* out = (float*)d_out;

    cudaFuncSetAttribute(spatial_attn_kernel,
                         cudaFuncAttributeMaxDynamicSharedMemorySize, SMEM_BYTES);

    prep_kernel<<<(DIN * G3 + 255) / 256, 256>>>(Wih, bih, bhh);
    spatial_attn_kernel<<<BB, NTHREADS, SMEM_BYTES>>>(
        local_inputs, global_inputs, local_states, global_states, distmat,
        la0, ga0, Wcl, bcl, Wll, bll, vl, Wcg, bcg, Wlg, blg, vg, out);
}

// round 2
// speedup vs baseline: 1.0389x; 1.0389x over previous
#include <cuda_runtime.h>
#include <cuda_fp16.h>
#include <math.h>

#define TT   24
#define BB   64
#define NI   32
#define IL   24
#define VEC  24
#define NS   256
#define HH   256
#define DIN  288
#define G3   768
#define LAM  0.2f
#define NTHREADS 1024
#define K2   144      // DIN/2
#define GW   384      // gate-phase threads (2 outputs each)

// --------- device scratch (no allocation allowed) ----------
__device__ uint2 g_Wh[K2 * GW];                 // fp16x2 packed Wih^T (i,g,o rows only)
__device__ __align__(8) float g_gbias[G3];

__device__ __forceinline__ float frcp(float x) {
    float y; asm("rcp.approx.f32 %0, %1;" : "=f"(y) : "f"(x)); return y;
}

__global__ void prep_kernel(const float* __restrict__ Wih,
                            const float* __restrict__ bih,
                            const float* __restrict__ bhh) {
    int idx = blockIdx.x * blockDim.x + threadIdx.x;
    int total = K2 * GW;
    for (int i = idx; i < total; i += gridDim.x * blockDim.x) {
        int k2 = i / GW, j = i - k2 * GW;
        int gg0 = 2 * j, gg1 = 2 * j + 1;
        int r0 = (gg0 < 256) ? gg0 : gg0 + 256;   // skip f rows
        int r1 = (gg1 < 256) ? gg1 : gg1 + 256;
        __half2 h0 = __floats2half2_rn(Wih[r0 * DIN + 2 * k2], Wih[r0 * DIN + 2 * k2 + 1]);
        __half2 h1 = __floats2half2_rn(Wih[r1 * DIN + 2 * k2], Wih[r1 * DIN + 2 * k2 + 1]);
        uint2 u; u.x = *(unsigned*)&h0; u.y = *(unsigned*)&h1;
        g_Wh[i] = u;
    }
    if (idx < G3) {
        int r = (idx < 256) ? idx : idx + 256;
        g_gbias[idx] = bih[r] + bhh[r];
    }
}

// ---------------- smem layout (floats) ----------------
#define U_OFF     0          // precompute: sWcg(18432)+sGs(8448); steady: sWll(6144)+sWlg(6144)
#define U_SIZE    26880
#define EG_OFF    (U_OFF + U_SIZE)     // 6144  e^{2*hf_g}
#define EL_OFF    (EG_OFF + 6144)      // 768   e^{2*hf_l}
#define GARR_OFF  (EL_OFF + 768)       // 768
#define XV_OFF    (GARR_OFF + 768)     // 288 (float2-aligned)
#define CV_OFF    (XV_OFF + 288)       // 256
#define TVL_OFF   (CV_OFF + 256)       // 48  (float2[24]: F_l, w_l)
#define TVG_OFF   (TVL_OFF + 48)       // 48  (float2[24]: F_g, w_g)
#define PSL_OFF   (TVG_OFF + 48)       // 768
#define PSG_OFF   (PSL_OFF + 768)      // 1024
#define SLV_OFF   (PSG_OFF + 1024)     // 32
#define SGV_OFF   (SLV_OFF + 32)       // 256
#define LAV_OFF   (SGV_OFF + 256)      // 32
#define GAV_OFF   (LAV_OFF + 32)       // 256
#define RED_OFF   (GAV_OFF + 256)      // 33
#define WLV_OFF   (RED_OFF + 33)       // 24
#define WGV_OFF   (WLV_OFF + 24)       // 24
#define SBLL_OFF  (WGV_OFF + 24)       // 24
#define SBLG_OFF  (SBLL_OFF + 24)      // 24
#define SGB_OFF   (SBLG_OFF + 24)      // 256  lam*distmat
#define SINP_OFF  (SGB_OFF + 256)      // 24*288 = 6912 preloaded inputs
#define SMEM_FLOATS (SINP_OFF + 6912)
#define SMEM_BYTES  (SMEM_FLOATS * 4)

__global__ __launch_bounds__(NTHREADS, 1)
void spatial_attn_kernel(
    const float* __restrict__ local_inputs,
    const float* __restrict__ global_inputs,
    const float* __restrict__ local_states,
    const float* __restrict__ global_states,
    const float* __restrict__ distmat,
    const float* __restrict__ la0,
    const float* __restrict__ ga0,
    const float* __restrict__ Wcl, const float* __restrict__ bcl,
    const float* __restrict__ Wll, const float* __restrict__ bll,
    const float* __restrict__ vl,
    const float* __restrict__ Wcg, const float* __restrict__ bcg,
    const float* __restrict__ Wlg, const float* __restrict__ blg,
    const float* __restrict__ vg,
    float* __restrict__ out)
{
    extern __shared__ float sm[];
    float* sWcg = sm + U_OFF;
    float* sGs  = sm + U_OFF + 18432;
    float* sWll = sm + U_OFF;
    float* sWlg = sm + U_OFF + 6144;
    float* Eg   = sm + EG_OFF;
    float* El   = sm + EL_OFF;
    float* garr = sm + GARR_OFF;
    float* xv   = sm + XV_OFF;
    float* cv   = sm + CV_OFF;
    float2* tvl = (float2*)(sm + TVL_OFF);
    float2* tvg = (float2*)(sm + TVG_OFF);
    float* psl  = sm + PSL_OFF;
    float* psg  = sm + PSG_OFF;
    float* slv  = sm + SLV_OFF;
    float* sgv  = sm + SGV_OFF;
    float* lav  = sm + LAV_OFF;
    float* gav  = sm + GAV_OFF;
    float* red  = sm + RED_OFF;
    float* wlv  = sm + WLV_OFF;
    float* wgv  = sm + WGV_OFF;
    float* sbll = sm + SBLL_OFF;
    float* sblg = sm + SBLG_OFF;
    float* sgb  = sm + SGB_OFF;
    float* sInp = sm + SINP_OFF;

    const int b = blockIdx.x;
    const int tid = threadIdx.x;
    const int w = tid >> 5, lane = tid & 31;

    // ---------- precompute El = exp(2*hf_l) ----------
    if (tid < G3) {
        int o = tid >> 5, l = tid & 31;
        float acc = __ldg(&bcl[o]);
        const float* ls = local_states + b * (NI * IL);
        #pragma unroll
        for (int c = 0; c < IL; c++)
            acc = fmaf(__ldg(&Wcl[o * IL + c]), __ldg(&ls[c * NI + l]), acc);
        El[tid] = __expf(2.f * acc);
    }

    // preload Wcg + all step inputs + constants
    for (int i = tid; i < VEC * IL * NI; i += NTHREADS) sWcg[i] = Wcg[i];
    for (int i = tid; i < TT * DIN; i += NTHREADS) {
        int t = i / DIN, k = i - t * DIN;
        sInp[i] = (k < NI) ? __ldg(&local_inputs[(t * BB + b) * NI + k])
                           : __ldg(&global_inputs[(t * BB + b) * NS + (k - NI)]);
    }
    if (tid < NS)  sgb[tid] = LAM * __ldg(&distmat[b * NS + tid]);
    if (tid < VEC) {
        wlv[tid]  = -2.f * __ldg(&vl[tid]);
        wgv[tid]  = -2.f * (1.f - LAM) * __ldg(&vg[tid]);
        sbll[tid] = __ldg(&bll[tid]);
        sblg[tid] = __ldg(&blg[tid]);
    }
    if (tid < NI)  lav[tid] = la0[b * NI + tid];
    if (tid < NS)  gav[tid] = ga0[b * NS + tid];
    __syncthreads();

    // ---------- precompute Eg = exp(2*hf_g): register-tiled GEMM ----------
    {
        int og = tid >> 7;       // 0..7  -> o block of 3
        int s0 = tid & 127;      // s in {s0, s0+128}
        float a00=0.f,a01=0.f,a10=0.f,a11=0.f,a20=0.f,a21=0.f;
        const float* gsb = global_states + (size_t)b * (NS * NI * IL);
        for (int c = 0; c < IL; c++) {
            __syncthreads();
            for (int i = tid; i < NS * NI; i += NTHREADS) {
                int s = i >> 5, j = i & 31;
                sGs[s * 33 + j] = gsb[c * (NS * NI) + i];
            }
            __syncthreads();
            #pragma unroll 8
            for (int j = 0; j < NI; j++) {
                float gA = sGs[s0 * 33 + j];
                float gB = sGs[(s0 + 128) * 33 + j];
                float w0 = sWcg[((og*3+0) * IL + c) * NI + j];
                float w1 = sWcg[((og*3+1) * IL + c) * NI + j];
                float w2 = sWcg[((og*3+2) * IL + c) * NI + j];
                a00 = fmaf(w0, gA, a00); a01 = fmaf(w0, gB, a01);
                a10 = fmaf(w1, gA, a10); a11 = fmaf(w1, gB, a11);
                a20 = fmaf(w2, gA, a20); a21 = fmaf(w2, gB, a21);
            }
        }
        float b0 = __ldg(&bcg[og*3+0]);
        float b1 = __ldg(&bcg[og*3+1]);
        float b2 = __ldg(&bcg[og*3+2]);
        __syncthreads();
        Eg[(og*3+0)*NS + s0      ] = __expf(2.f * (a00 + b0));
        Eg[(og*3+0)*NS + s0 + 128] = __expf(2.f * (a01 + b0));
        Eg[(og*3+1)*NS + s0      ] = __expf(2.f * (a10 + b1));
        Eg[(og*3+1)*NS + s0 + 128] = __expf(2.f * (a11 + b1));
        Eg[(og*3+2)*NS + s0      ] = __expf(2.f * (a20 + b2));
        Eg[(og*3+2)*NS + s0 + 128] = __expf(2.f * (a21 + b2));
    }
    __syncthreads();

    // steady-state: Wll/Wlg into smem (reuses precompute region)
    for (int i = tid; i < VEC * HH; i += NTHREADS) { sWll[i] = Wll[i]; sWlg[i] = Wlg[i]; }
    __syncthreads();

    // hoist E into registers for the whole scan
    float Ereg[6];
    {
        int grp = tid >> 8, s = tid & 255;
        #pragma unroll
        for (int oi = 0; oi < 6; oi++) Ereg[oi] = Eg[(grp * 6 + oi) * NS + s];
    }
    float Elreg = (tid < G3) ? El[tid] : 0.f;

    float* out_h  = out;
    float* out_c  = out + TT * BB * HH;
    float* out_la = out_c + BB * HH;
    float* out_ga = out_la + TT * BB * NI;

    for (int t = 0; t < TT; t++) {
        // x = [la*l_inp, ga*g_inp] (inputs already in smem)
        if (tid < NI)        xv[tid] = lav[tid] * sInp[t * DIN + tid];
        else if (tid < DIN)  xv[tid] = gav[tid - NI] * sInp[t * DIN + tid];
        __syncthreads();

        // gates (i,g,o): fp16 weights, fp32 math, 2 outputs/thread
        if (tid < GW) {
            const uint2* wp = g_Wh + tid;
            float2 bias = ((const float2*)g_gbias)[tid];
            float a0 = bias.x, a1 = bias.y;
            const float2* xv2 = (const float2*)xv;
            #pragma unroll 4
            for (int k2 = 0; k2 < K2; k2++) {
                uint2 ww = wp[k2 * GW];
                float2 x2 = xv2[k2];
                float2 f0 = __half22float2(*(__half2*)&ww.x);
                float2 f1 = __half22float2(*(__half2*)&ww.y);
                a0 = fmaf(x2.x, f0.x, a0); a0 = fmaf(x2.y, f0.y, a0);
                a1 = fmaf(x2.x, f1.x, a1); a1 = fmaf(x2.y, f1.y, a1);
            }
            garr[2 * tid] = a0; garr[2 * tid + 1] = a1;
        }
        __syncthreads();

        // LSTM (h0=c0=0): c = sig(i)*tanh(g); h = sig(o)*tanh(c)
        if (tid < HH) {
            float ig = garr[tid], gg = garr[256 + tid], og = garr[512 + tid];
            float si = 1.f / (1.f + __expf(-ig));
            float cval = si * tanhf(gg);
            float so = 1.f / (1.f + __expf(-og));
            cv[tid] = cval;
            out_h[(size_t)(t * BB + b) * HH + tid] = so * tanhf(cval);
            if (t == TT - 1) out_c[(size_t)b * HH + tid] = cval;
        }
        __syncthreads();

        // y_l[d], y_g[d] + F = exp(2y) fused into the reduction warps
        if (w < VEC) {
            float a = 0.f, bg = 0.f;
            const float* wr  = sWll + w * HH;
            const float* wr2 = sWlg + w * HH;
            #pragma unroll
            for (int i = 0; i < HH / 32; i++) {
                float cc = cv[lane + 32 * i];
                a  = fmaf(cc, wr[lane + 32 * i], a);
                bg = fmaf(cc, wr2[lane + 32 * i], bg);
            }
            #pragma unroll
            for (int off = 16; off; off >>= 1) {
                a  += __shfl_xor_sync(0xffffffffu, a, off);
                bg += __shfl_xor_sync(0xffffffffu, bg, off);
            }
            if (lane == 0) {
                tvl[w] = make_float2(__expf(2.f * (a  + sbll[w])), wlv[w]);
                tvg[w] = make_float2(__expf(2.f * (bg + sblg[w])), wgv[w]);
            }
        }
        __syncthreads();

        // partials: tanh(a+y) = 1 - 2/(1+E*F); constants dropped (softmax-invariant)
        {
            float acc = 0.f;
            #pragma unroll 4
            for (int d = 0; d < VEC; d++) {
                float2 p = tvg[d];
                #pragma unroll
                for (int oi = 0; oi < 6; oi++)
                    acc = fmaf(p.y, frcp(fmaf(Ereg[oi], p.x, 1.f)), acc);
            }
            psg[tid] = acc;
        }
        if (tid < G3) {
            float acc = 0.f;
            #pragma unroll 4
            for (int d = 0; d < VEC; d++) {
                float2 p = tvl[d];
                acc = fmaf(p.y, frcp(fmaf(Elreg, p.x, 1.f)), acc);
            }
            psl[tid] = acc;
        }
        __syncthreads();

        // reduce partials (+ lam*distmat base for global)
        if (tid < NS) {
            sgv[tid] = sgb[tid] + (psg[tid] + psg[256 + tid] + psg[512 + tid] + psg[768 + tid]);
        } else if (tid < NS + NI) {
            int l = tid - NS;
            float a = 0.f;
            #pragma unroll
            for (int o = 0; o < VEC; o++) a += psl[o * NI + l];
            slv[l] = a;
        }
        __syncthreads();

        // softmax over s_g (warps 0..7)
        if (tid < NS) {
            float v = sgv[tid];
            float m = v;
            #pragma unroll
            for (int off = 16; off; off >>= 1) m = fmaxf(m, __shfl_xor_sync(0xffffffffu, m, off));
            if (lane == 0) red[w] = m;
        }
        __syncthreads();
        if (tid < NS) {
            float m = fmaxf(fmaxf(fmaxf(red[0], red[1]), fmaxf(red[2], red[3])),
                            fmaxf(fmaxf(red[4], red[5]), fmaxf(red[6], red[7])));
            float e = __expf(sgv[tid] - m);
            sgv[tid] = e;
            float su = e;
            #pragma unroll
            for (int off = 16; off; off >>= 1) su += __shfl_xor_sync(0xffffffffu, su, off);
            if (lane == 0) red[8 + w] = su;
        }
        // softmax over s_l (warp 16)
        if (w == 16) {
            float v = slv[lane];
            float m = v;
            #pragma unroll
            for (int off = 16; off; off >>= 1) m = fmaxf(m, __shfl_xor_sync(0xffffffffu, m, off));
            float e = __expf(v - m);
            float su = e;
            #pragma unroll
            for (int off = 16; off; off >>= 1) su += __shfl_xor_sync(0xffffffffu, su, off);
            float a = e / su;
            lav[lane] = a;
            out_la[(size_t)(t * BB + b) * NI + lane] = a;
        }
        __syncthreads();
        if (tid < NS) {
            float su = red[8] + red[9] + red[10] + red[11] + red[12] + red[13] + red[14] + red[15];
            float a = sgv[tid] / su;
            gav[tid] = a;
            out_ga[(size_t)(t * BB + b) * NS + tid] = a;
        }
        __syncthreads();
    }
}

extern "C" void kernel_launch(void* const* d_in, const int* in_sizes, int n_in,
                              void* d_out, int out_size) {
    const float* local_inputs  = (const float*)d_in[0];
    const float* global_inputs = (const float*)d_in[1];
    const float* local_states  = (const float*)d_in[2];
    const float* global_states = (const float*)d_in[3];
    const float* distmat       = (const float*)d_in[4];
    const float* la0           = (const float*)d_in[5];
    const float* ga0           = (const float*)d_in[6];
    const float* Wcl = (const float*)d_in[7];
    const float* bcl = (const float*)d_in[8];
    const float* Wll = (const float*)d_in[9];
    const float* bll = (const float*)d_in[10];
    const float* vl  = (const float*)d_in[11];
    const float* Wcg = (const float*)d_in[12];
    const float* bcg = (const float*)d_in[13];
    const float* Wlg = (const float*)d_in[14];
    const float* blg = (const float*)d_in[15];
    const float* vg  = (const float*)d_in[16];
    const float* Wih = (const float*)d_in[17];
    const float* bih = (const float*)d_in[18];
    const float* bhh = (const float*)d_in[19];
    float* out = (float*)d_out;

    cudaFuncSetAttribute(spatial_attn_kernel,
                         cudaFuncAttributeMaxDynamicSharedMemorySize, SMEM_BYTES);

    prep_kernel<<<(K2 * GW + 255) / 256, 256>>>(Wih, bih, bhh);
    spatial_attn_kernel<<<BB, NTHREADS, SMEM_BYTES>>>(
        local_inputs, global_inputs, local_states, global_states, distmat,
        la0, ga0, Wcl, bcl, Wll, bll, vl, Wcg, bcg, Wlg, blg, vg, out);
}

// round 3
// speedup vs baseline: 1.6144x; 1.5540x over previous
#include <cuda_runtime.h>
#include <cuda_fp16.h>
#include <math.h>

#define TT   24
#define BB   64
#define NI   32
#define IL   24
#define VEC  24
#define NS   256
#define HH   256
#define DIN  288
#define G3   768
#define LAM  0.2f
#define NTHREADS 1024
#define KC   36        // DIN/8 chunks of 8 fp16 weights

// --------- device scratch ----------
__device__ uint4 g_W4[KC * G3];     // [kc][j] : 8 fp16 weights (k = 8kc..8kc+7) of output j
__device__ float g_gbias[G3];

__device__ __forceinline__ float frcp(float x) {
    float y; asm("rcp.approx.f32 %0, %1;" : "=f"(y) : "f"(x)); return y;
}

__global__ void prep_kernel(const float* __restrict__ Wih,
                            const float* __restrict__ bih,
                            const float* __restrict__ bhh) {
    int idx = blockIdx.x * blockDim.x + threadIdx.x;
    int total = KC * G3;
    for (int i = idx; i < total; i += gridDim.x * blockDim.x) {
        int kc = i / G3, j = i - kc * G3;
        int r = (j < 256) ? j : j + 256;    // skip f-gate rows
        const float* src = Wih + r * DIN + kc * 8;
        __half2 h0 = __floats2half2_rn(src[0], src[1]);
        __half2 h1 = __floats2half2_rn(src[2], src[3]);
        __half2 h2 = __floats2half2_rn(src[4], src[5]);
        __half2 h3 = __floats2half2_rn(src[6], src[7]);
        uint4 u;
        u.x = *(unsigned*)&h0; u.y = *(unsigned*)&h1;
        u.z = *(unsigned*)&h2; u.w = *(unsigned*)&h3;
        g_W4[i] = u;
    }
    if (idx < G3) {
        int r = (idx < 256) ? idx : idx + 256;
        g_gbias[idx] = bih[r] + bhh[r];
    }
}

// ---------------- smem layout (floats) ----------------
#define U_OFF     0          // precompute: sWcg(18432)+sGs(8448); steady: sWll+sWlg (12288)
#define U_SIZE    26880
#define EG_OFF    (U_OFF + U_SIZE)     // 6144
#define GARR_OFF  (EG_OFF + 6144)      // 768
#define XV_OFF    (GARR_OFF + 768)     // 288, 16B aligned
#define CV_OFF    (XV_OFF + 288)       // 256
#define TVL_OFF   (CV_OFF + 256)       // 48 (float2[24]: F, w)
#define TVG_OFF   (TVL_OFF + 48)       // 48
#define PSL_OFF   (TVG_OFF + 48)       // 768
#define PSG_OFF   (PSL_OFF + 768)      // 1024
#define SLV_OFF   (PSG_OFF + 1024)     // 32
#define RED_OFF   (SLV_OFF + 32)       // 36
#define SBLL_OFF  (RED_OFF + 36)       // 24
#define SBLG_OFF  (SBLL_OFF + 24)      // 24
#define SGB_OFF   (SBLG_OFF + 24)      // 256
#define SINP_OFF  (SGB_OFF + 256)      // 24*288 = 6912
#define SMEM_FLOATS (SINP_OFF + 6912)
#define SMEM_BYTES  (SMEM_FLOATS * 4)

__global__ __launch_bounds__(NTHREADS, 1)
void spatial_attn_kernel(
    const float* __restrict__ local_inputs,
    const float* __restrict__ global_inputs,
    const float* __restrict__ local_states,
    const float* __restrict__ global_states,
    const float* __restrict__ distmat,
    const float* __restrict__ la0,
    const float* __restrict__ ga0,
    const float* __restrict__ Wcl, const float* __restrict__ bcl,
    const float* __restrict__ Wll, const float* __restrict__ bll,
    const float* __restrict__ vl,
    const float* __restrict__ Wcg, const float* __restrict__ bcg,
    const float* __restrict__ Wlg, const float* __restrict__ blg,
    const float* __restrict__ vg,
    float* __restrict__ out)
{
    extern __shared__ float sm[];
    float* sWcg = sm + U_OFF;
    float* sGs  = sm + U_OFF + 18432;
    float* sWll = sm + U_OFF;
    float* sWlg = sm + U_OFF + 6144;
    float* Eg   = sm + EG_OFF;
    float* garr = sm + GARR_OFF;
    float* xv   = sm + XV_OFF;
    float* cv   = sm + CV_OFF;
    float2* tvl = (float2*)(sm + TVL_OFF);
    float2* tvg = (float2*)(sm + TVG_OFF);
    float* psl  = sm + PSL_OFF;
    float* psg  = sm + PSG_OFF;
    float* slv  = sm + SLV_OFF;
    float* red  = sm + RED_OFF;
    float* sbll = sm + SBLL_OFF;
    float* sblg = sm + SBLG_OFF;
    float* sgb  = sm + SGB_OFF;
    float* sInp = sm + SINP_OFF;

    const int b = blockIdx.x;
    const int tid = threadIdx.x;
    const int w = tid >> 5, lane = tid & 31;

    // ---------- El (local conv) directly into register of the owning thread ----------
    float Elreg = 0.f;
    if (tid < G3) {
        int o = tid >> 5, l = tid & 31;
        float acc = __ldg(&bcl[o]);
        const float* ls = local_states + b * (NI * IL);
        #pragma unroll
        for (int c = 0; c < IL; c++)
            acc = fmaf(__ldg(&Wcl[o * IL + c]), __ldg(&ls[c * NI + l]), acc);
        Elreg = __expf(2.f * acc);
    }

    // preload Wcg + step inputs + constants
    for (int i = tid; i < VEC * IL * NI; i += NTHREADS) sWcg[i] = Wcg[i];
    for (int i = tid; i < TT * DIN; i += NTHREADS) {
        int t = i / DIN, k = i - t * DIN;
        sInp[i] = (k < NI) ? __ldg(&local_inputs[(t * BB + b) * NI + k])
                           : __ldg(&global_inputs[(t * BB + b) * NS + (k - NI)]);
    }
    if (tid < NS)  sgb[tid] = LAM * __ldg(&distmat[b * NS + tid]);
    if (tid < VEC) {
        sbll[tid] = __ldg(&bll[tid]);
        sblg[tid] = __ldg(&blg[tid]);
    }
    __syncthreads();

    // xv for t=0 (sInp now visible)
    if (tid < NI)        xv[tid] = __ldg(&la0[b * NI + tid]) * sInp[tid];
    else if (tid < DIN)  xv[tid] = __ldg(&ga0[b * NS + (tid - NI)]) * sInp[tid];

    // ---------- precompute Eg = exp(2*hf_g): register-tiled GEMM ----------
    {
        int og = tid >> 7;       // 0..7 -> o block of 3
        int s0 = tid & 127;      // s in {s0, s0+128}
        float a00=0.f,a01=0.f,a10=0.f,a11=0.f,a20=0.f,a21=0.f;
        const float* gsb = global_states + (size_t)b * (NS * NI * IL);
        for (int c = 0; c < IL; c++) {
            __syncthreads();
            for (int i = tid; i < NS * NI; i += NTHREADS) {
                int s = i >> 5, j = i & 31;
                sGs[s * 33 + j] = gsb[c * (NS * NI) + i];
            }
            __syncthreads();
            #pragma unroll 8
            for (int j = 0; j < NI; j++) {
                float gA = sGs[s0 * 33 + j];
                float gB = sGs[(s0 + 128) * 33 + j];
                float w0 = sWcg[((og*3+0) * IL + c) * NI + j];
                float w1 = sWcg[((og*3+1) * IL + c) * NI + j];
                float w2 = sWcg[((og*3+2) * IL + c) * NI + j];
                a00 = fmaf(w0, gA, a00); a01 = fmaf(w0, gB, a01);
                a10 = fmaf(w1, gA, a10); a11 = fmaf(w1, gB, a11);
                a20 = fmaf(w2, gA, a20); a21 = fmaf(w2, gB, a21);
            }
        }
        float b0 = __ldg(&bcg[og*3+0]);
        float b1 = __ldg(&bcg[og*3+1]);
        float b2 = __ldg(&bcg[og*3+2]);
        __syncthreads();
        Eg[(og*3+0)*NS + s0      ] = __expf(2.f * (a00 + b0));
        Eg[(og*3+0)*NS + s0 + 128] = __expf(2.f * (a01 + b0));
        Eg[(og*3+1)*NS + s0      ] = __expf(2.f * (a10 + b1));
        Eg[(og*3+1)*NS + s0 + 128] = __expf(2.f * (a11 + b1));
        Eg[(og*3+2)*NS + s0      ] = __expf(2.f * (a20 + b2));
        Eg[(og*3+2)*NS + s0 + 128] = __expf(2.f * (a21 + b2));
    }
    __syncthreads();

    // steady-state Wll/Wlg into smem
    for (int i = tid; i < VEC * HH; i += NTHREADS) { sWll[i] = Wll[i]; sWlg[i] = Wlg[i]; }
    __syncthreads();

    // hoist per-thread constants
    float Ereg[6];
    {
        int grp = tid >> 8, s = tid & 255;
        #pragma unroll
        for (int oi = 0; oi < 6; oi++) Ereg[oi] = Eg[(grp * 6 + oi) * NS + s];
    }
    float biasreg = (tid < G3) ? g_gbias[tid] : 0.f;
    float wlreg   = (w < VEC && lane == 0) ? -2.f * __ldg(&vl[w]) : 0.f;
    float wgreg   = (w < VEC && lane == 0) ? -2.f * (1.f - LAM) * __ldg(&vg[w]) : 0.f;

    float* out_h  = out;
    float* out_c  = out + TT * BB * HH;
    float* out_la = out_c + BB * HH;
    float* out_ga = out_la + TT * BB * NI;

    for (int t = 0; t < TT; t++) {
        // ---- gates (i,g,o): 768 threads, one output each, LDG.128 fp16 ----
        if (tid < G3) {
            float a0 = biasreg, a1 = 0.f;
            const uint4* wp = g_W4 + tid;
            const float4* xv4 = (const float4*)xv;
            #pragma unroll 6
            for (int kc = 0; kc < KC; kc++) {
                uint4 ww = wp[kc * G3];
                float4 xa = xv4[2 * kc], xb = xv4[2 * kc + 1];
                float2 f0 = __half22float2(*(__half2*)&ww.x);
                float2 f1 = __half22float2(*(__half2*)&ww.y);
                float2 f2 = __half22float2(*(__half2*)&ww.z);
                float2 f3 = __half22float2(*(__half2*)&ww.w);
                a0 = fmaf(xa.x, f0.x, a0); a1 = fmaf(xa.y, f0.y, a1);
                a0 = fmaf(xa.z, f1.x, a0); a1 = fmaf(xa.w, f1.y, a1);
                a0 = fmaf(xb.x, f2.x, a0); a1 = fmaf(xb.y, f2.y, a1);
                a0 = fmaf(xb.z, f3.x, a0); a1 = fmaf(xb.w, f3.y, a1);
            }
            garr[tid] = a0 + a1;
        }
        __syncthreads();   // B1

        // ---- LSTM (h0=c0=0), exp-form activations ----
        if (tid < HH) {
            float ig = garr[tid], gg = garr[256 + tid], og = garr[512 + tid];
            float si = frcp(1.f + __expf(-ig));
            float tg = fmaf(-2.f, frcp(1.f + __expf(2.f * gg)), 1.f);
            float cval = si * tg;
            float so = frcp(1.f + __expf(-og));
            float tc = fmaf(-2.f, frcp(1.f + __expf(2.f * cval)), 1.f);
            cv[tid] = cval;
            out_h[(size_t)(t * BB + b) * HH + tid] = so * tc;
            if (t == TT - 1) out_c[(size_t)b * HH + tid] = cval;
        }
        __syncthreads();   // B2

        // ---- y_l, y_g dot products + F = exp(2y) ----
        if (w < VEC) {
            float a = 0.f, bg = 0.f;
            const float* wr  = sWll + w * HH;
            const float* wr2 = sWlg + w * HH;
            #pragma unroll
            for (int i = 0; i < HH / 32; i++) {
                float cc = cv[lane + 32 * i];
                a  = fmaf(cc, wr[lane + 32 * i], a);
                bg = fmaf(cc, wr2[lane + 32 * i], bg);
            }
            #pragma unroll
            for (int off = 16; off; off >>= 1) {
                a  += __shfl_xor_sync(0xffffffffu, a, off);
                bg += __shfl_xor_sync(0xffffffffu, bg, off);
            }
            if (lane == 0) {
                tvl[w] = make_float2(__expf(2.f * (a  + sbll[w])), wlreg);
                tvg[w] = make_float2(__expf(2.f * (bg + sblg[w])), wgreg);
            }
        }
        __syncthreads();   // B3

        // ---- partials: quad-grouped  Σ w/(1+E·F) -> 1 rcp per 4 terms ----
        {
            float acc = 0.f;
            #pragma unroll
            for (int dq = 0; dq < 6; dq++) {
                float2 q0 = tvg[4*dq+0], q1 = tvg[4*dq+1];
                float2 q2 = tvg[4*dq+2], q3 = tvg[4*dq+3];
                #pragma unroll
                for (int oi = 0; oi < 6; oi++) {
                    float E = Ereg[oi];
                    float d1 = fmaf(E, q0.x, 1.f), d2 = fmaf(E, q1.x, 1.f);
                    float d3 = fmaf(E, q2.x, 1.f), d4 = fmaf(E, q3.x, 1.f);
                    float p12 = d1 * d2, p34 = d3 * d4;
                    float n12 = q0.y * d2; n12 = fmaf(q1.y, d1, n12);
                    float n34 = q2.y * d4; n34 = fmaf(q3.y, d3, n34);
                    float num = n12 * p34; num = fmaf(n34, p12, num);
                    acc = fmaf(num, frcp(p12 * p34), acc);
                }
            }
            psg[tid] = acc;
        }
        if (tid < G3) {
            float acc = 0.f, E = Elreg;
            #pragma unroll
            for (int dq = 0; dq < 6; dq++) {
                float2 q0 = tvl[4*dq+0], q1 = tvl[4*dq+1];
                float2 q2 = tvl[4*dq+2], q3 = tvl[4*dq+3];
                float d1 = fmaf(E, q0.x, 1.f), d2 = fmaf(E, q1.x, 1.f);
                float d3 = fmaf(E, q2.x, 1.f), d4 = fmaf(E, q3.x, 1.f);
                float p12 = d1 * d2, p34 = d3 * d4;
                float n12 = q0.y * d2; n12 = fmaf(q1.y, d1, n12);
                float n34 = q2.y * d4; n34 = fmaf(q3.y, d3, n34);
                float num = n12 * p34; num = fmaf(n34, p12, num);
                acc = fmaf(num, frcp(p12 * p34), acc);
            }
            psl[tid] = acc;
        }
        __syncthreads();   // B4

        // ---- reduce + warp max (merged) ----
        float vreg = 0.f, ereg = 0.f;
        if (tid < NS) {
            vreg = sgb[tid] + (psg[tid] + psg[256 + tid] + psg[512 + tid] + psg[768 + tid]);
            float m = vreg;
            #pragma unroll
            for (int off = 16; off; off >>= 1) m = fmaxf(m, __shfl_xor_sync(0xffffffffu, m, off));
            if (lane == 0) red[w] = m;
        } else if (tid < NS + NI) {
            int l = tid - NS;
            float a = 0.f;
            #pragma unroll
            for (int o = 0; o < VEC; o++) a += psl[o * NI + l];
            slv[l] = a;
        }
        __syncthreads();   // B5

        // ---- global exp + warp sums; local softmax (warp 16) ----
        if (tid < NS) {
            float m = fmaxf(fmaxf(fmaxf(red[0], red[1]), fmaxf(red[2], red[3])),
                            fmaxf(fmaxf(red[4], red[5]), fmaxf(red[6], red[7])));
            ereg = __expf(vreg - m);
            float su = ereg;
            #pragma unroll
            for (int off = 16; off; off >>= 1) su += __shfl_xor_sync(0xffffffffu, su, off);
            if (lane == 0) red[8 + w] = su;
        }
        if (w == 16) {
            float v = slv[lane];
            float m = v;
            #pragma unroll
            for (int off = 16; off; off >>= 1) m = fmaxf(m, __shfl_xor_sync(0xffffffffu, m, off));
            float e = __expf(v - m);
            float su = e;
            #pragma unroll
            for (int off = 16; off; off >>= 1) su += __shfl_xor_sync(0xffffffffu, su, off);
            float a = e * frcp(su);
            out_la[(size_t)(t * BB + b) * NI + lane] = a;
            if (t + 1 < TT) xv[lane] = a * sInp[(t + 1) * DIN + lane];
        }
        __syncthreads();   // B6

        // ---- global normalize + write + next-step xv ----
        if (tid < NS) {
            float su = red[8] + red[9] + red[10] + red[11]
                     + red[12] + red[13] + red[14] + red[15];
            float a = ereg * frcp(su);
            out_ga[(size_t)(t * BB + b) * NS + tid] = a;
            if (t + 1 < TT) xv[NI + tid] = a * sInp[(t + 1) * DIN + NI + tid];
        }
        __syncthreads();   // B7
    }
}

extern "C" void kernel_launch(void* const* d_in, const int* in_sizes, int n_in,
                              void* d_out, int out_size) {
    const float* local_inputs  = (const float*)d_in[0];
    const float* global_inputs = (const float*)d_in[1];
    const float* local_states  = (const float*)d_in[2];
    const float* global_states = (const float*)d_in[3];
    const float* distmat       = (const float*)d_in[4];
    const float* la0           = (const float*)d_in[5];
    const float* ga0           = (const float*)d_in[6];
    const float* Wcl = (const float*)d_in[7];
    const float* bcl = (const float*)d_in[8];
    const float* Wll = (const float*)d_in[9];
    const float* bll = (const float*)d_in[10];
    const float* vl  = (const float*)d_in[11];
    const float* Wcg = (const float*)d_in[12];
    const float* bcg = (const float*)d_in[13];
    const float* Wlg = (const float*)d_in[14];
    const float* blg = (const float*)d_in[15];
    const float* vg  = (const float*)d_in[16];
    const float* Wih = (const float*)d_in[17];
    const float* bih = (const float*)d_in[18];
    const float* bhh = (const float*)d_in[19];
    float* out = (float*)d_out;

    cudaFuncSetAttribute(spatial_attn_kernel,
                         cudaFuncAttributeMaxDynamicSharedMemorySize, SMEM_BYTES);

    prep_kernel<<<(KC * G3 + 255) / 256, 256>>>(Wih, bih, bhh);
    spatial_attn_kernel<<<BB, NTHREADS, SMEM_BYTES>>>(
        local_inputs, global_inputs, local_states, global_states, distmat,
        la0, ga0, Wcl, bcl, Wll, bll, vl, Wcg, bcg, Wlg, blg, vg, out);
}

// round 5
// speedup vs baseline: 2.3843x; 1.4769x over previous
#include <cuda_runtime.h>
#include <cuda_fp16.h>
#include <cstdint>
#include <math.h>

#define TT   24
#define BB   64
#define NI   32
#define IL   24
#define VEC  24
#define NS   256
#define HH   256
#define DIN  288
#define LAM  0.2f
#define NTHREADS 1024
#define KC   36        // DIN/8 chunks
#define JJ   384       // gate outputs per rank (i,g,o x 128)
#define OHALF 12       // o-range per rank

// --------- device scratch ----------
__device__ uint4 g_W4c[2 * KC * JJ];   // [r][kc][jj]
__device__ float g_gbiasC[2 * JJ];

__device__ __forceinline__ float frcp(float x) {
    float y; asm("rcp.approx.f32 %0, %1;" : "=f"(y) : "f"(x)); return y;
}
__device__ __forceinline__ unsigned s2u(const void* p) {
    unsigned a; asm("{ .reg .u64 t; cvta.to.shared.u64 t, %1; cvt.u32.u64 %0, t; }" : "=r"(a) : "l"(p)); return a;
}
__device__ __forceinline__ unsigned mapa_u32(unsigned a, unsigned r) {
    unsigned o; asm("mapa.shared::cluster.u32 %0, %1, %2;" : "=r"(o) : "r"(a), "r"(r)); return o;
}
__device__ __forceinline__ void stc_f32(unsigned a, float v) {
    asm volatile("st.shared::cluster.f32 [%0], %1;" :: "r"(a), "f"(v) : "memory");
}
__device__ __forceinline__ void stc_b64(unsigned a, float x, float y) {
    unsigned long long u; asm("mov.b64 %0, {%1,%2};" : "=l"(u) : "f"(x), "f"(y));
    asm volatile("st.shared::cluster.b64 [%0], %1;" :: "r"(a), "l"(u) : "memory");
}
__device__ __forceinline__ void mbar_init(unsigned a, unsigned c) {
    asm volatile("mbarrier.init.shared.b64 [%0], %1;" :: "r"(a), "r"(c) : "memory");
}
__device__ __forceinline__ void mbar_arrive_remote(unsigned a) {
    asm volatile("mbarrier.arrive.release.cluster.shared::cluster.b64 _, [%0];" :: "r"(a) : "memory");
}
__device__ __forceinline__ void mbar_wait(unsigned a, unsigned ph) {
    unsigned done;
    asm volatile("{ .reg .pred p; mbarrier.try_wait.parity.acquire.cluster.shared::cta.b64 p, [%1], %2; selp.b32 %0,1,0,p; }"
        : "=r"(done) : "r"(a), "r"(ph) : "memory");
    while (!done) {
        asm volatile("{ .reg .pred p; mbarrier.try_wait.parity.acquire.cluster.shared::cta.b64 p, [%1], %2, 0x989680; selp.b32 %0,1,0,p; }"
            : "=r"(done) : "r"(a), "r"(ph) : "memory");
    }
}
__device__ __forceinline__ unsigned ctarank() {
    unsigned r; asm("mov.u32 %0, %%cluster_ctarank;" : "=r"(r)); return r;
}
__device__ __forceinline__ void cluster_sync_all() {
    asm volatile("barrier.cluster.arrive.aligned;" ::: "memory");
    asm volatile("barrier.cluster.wait.aligned;" ::: "memory");
}

__global__ void prep_kernel(const float* __restrict__ Wih,
                            const float* __restrict__ bih,
                            const float* __restrict__ bhh) {
    int idx = blockIdx.x * blockDim.x + threadIdx.x;
    int total = 2 * KC * JJ;
    for (int i = idx; i < total; i += gridDim.x * blockDim.x) {
        int r  = i / (KC * JJ);
        int rem = i - r * (KC * JJ);
        int kc = rem / JJ, jj = rem - kc * JJ;
        int h = 128 * r + (jj & 127);
        int row = (jj < 128) ? h : (jj < 256) ? (512 + h) : (768 + h);
        const float* src = Wih + row * DIN + kc * 8;
        __half2 h0 = __floats2half2_rn(src[0], src[1]);
        __half2 h1 = __floats2half2_rn(src[2], src[3]);
        __half2 h2 = __floats2half2_rn(src[4], src[5]);
        __half2 h3 = __floats2half2_rn(src[6], src[7]);
        uint4 u;
        u.x = *(unsigned*)&h0; u.y = *(unsigned*)&h1;
        u.z = *(unsigned*)&h2; u.w = *(unsigned*)&h3;
        g_W4c[i] = u;
    }
    if (idx < 2 * JJ) {
        int r = idx / JJ, jj = idx - r * JJ;
        int h = 128 * r + (jj & 127);
        int row = (jj < 128) ? h : (jj < 256) ? (512 + h) : (768 + h);
        g_gbiasC[idx] = bih[row] + bhh[row];
    }
}

// ---------------- smem layout (floats) ----------------
#define A_OFF     0          // precompute: sWcgH(9216)+sGs(8448)=17664 ; steady: sWll(3072)+sWlg(3072)
#define A_SIZE    17664
#define EG_OFF    (A_OFF + A_SIZE)     // 3072
#define SINP_OFF  (EG_OFF + 3072)      // 6912
#define SGB_OFF   (SINP_OFF + 6912)    // 256
#define GARR_OFF  (SGB_OFF + 256)      // 768
#define XV_OFF    (GARR_OFF + 768)     // 288 (16B aligned)
#define CVL_OFF   (XV_OFF + 288)       // 128
#define YMINE_OFF (CVL_OFF + 128)      // 48 (float2[24])
#define YPEER_OFF (YMINE_OFF + 48)     // 48
#define TVL_OFF   (YPEER_OFF + 48)     // 48 (float2[24], 16B aligned)
#define TVG_OFF   (TVL_OFF + 48)       // 48
#define PSG_OFF   (TVG_OFF + 48)       // 1024
#define PSL_OFF   (PSG_OFF + 1024)     // 384
#define SGP_OFF   (PSL_OFF + 384)      // 256 (peer-written global partial)
#define SLP_OFF   (SGP_OFF + 256)      // 32  (peer-written local partial)
#define RED_OFF   (SLP_OFF + 32)       // 36
#define MBAR_OFF  (RED_OFF + 36)       // 4 floats: E1 bar, E2 bar (8B each)
#define SMEM_FLOATS (MBAR_OFF + 4)
#define SMEM_BYTES  (SMEM_FLOATS * 4)

__global__ __launch_bounds__(NTHREADS, 1) __cluster_dims__(2, 1, 1)
void spatial_attn_kernel(
    const float* __restrict__ local_inputs,
    const float* __restrict__ global_inputs,
    const float* __restrict__ local_states,
    const float* __restrict__ global_states,
    const float* __restrict__ distmat,
    const float* __restrict__ la0,
    const float* __restrict__ ga0,
    const float* __restrict__ Wcl, const float* __restrict__ bcl,
    const float* __restrict__ Wll, const float* __restrict__ bll,
    const float* __restrict__ vl,
    const float* __restrict__ Wcg, const float* __restrict__ bcg,
    const float* __restrict__ Wlg, const float* __restrict__ blg,
    const float* __restrict__ vg,
    float* __restrict__ out)
{
    extern __shared__ float sm[];
    float*  sWcgH = sm + A_OFF;            // precompute: 12 o-rows of Wcg
    float*  sGs   = sm + A_OFF + 9216;     // 256*33 padded
    float*  sWll  = sm + A_OFF;            // steady: [24][128] (this rank's h-half)
    float*  sWlg  = sm + A_OFF + 3072;
    float*  Eg    = sm + EG_OFF;           // [12][256]
    float*  sInp  = sm + SINP_OFF;
    float*  sgb   = sm + SGB_OFF;
    float*  garr  = sm + GARR_OFF;         // 768: [khalf][384]
    float*  xv    = sm + XV_OFF;
    float*  cvl   = sm + CVL_OFF;          // 128 local c
    float2* ymine = (float2*)(sm + YMINE_OFF);
    float2* ypeer = (float2*)(sm + YPEER_OFF);
    float2* tvl   = (float2*)(sm + TVL_OFF);
    float2* tvg   = (float2*)(sm + TVG_OFF);
    float*  psg   = sm + PSG_OFF;
    float*  psl   = sm + PSL_OFF;
    float*  sgp   = sm + SGP_OFF;
    float*  slp   = sm + SLP_OFF;
    float*  red   = sm + RED_OFF;

    const int b   = blockIdx.x >> 1;
    const unsigned r = ctarank();
    const int tid = threadIdx.x;
    const int w = tid >> 5, lane = tid & 31;

    // shared/cluster addresses
    const unsigned barE1 = s2u(sm + MBAR_OFF);
    const unsigned barE2 = barE1 + 8;
    if (tid == 0) { mbar_init(barE1, 24); mbar_init(barE2, 288); }
    const unsigned peer = r ^ 1u;
    const unsigned p_ypeer = mapa_u32(s2u(sm + YPEER_OFF), peer);
    const unsigned p_sgp   = mapa_u32(s2u(sm + SGP_OFF), peer);
    const unsigned p_slp   = mapa_u32(s2u(sm + SLP_OFF), peer);
    const unsigned p_barE1 = mapa_u32(barE1, peer);
    const unsigned p_barE2 = mapa_u32(barE2, peer);

    // ---------- El (local conv) for this rank's 12 o's ----------
    float Elreg = 0.f;
    if (tid < OHALF * NI) {   // 384
        int o = OHALF * r + (tid >> 5), l = tid & 31;
        float acc = __ldg(&bcl[o]);
        const float* ls = local_states + b * (NI * IL);
        #pragma unroll
        for (int c = 0; c < IL; c++)
            acc = fmaf(__ldg(&Wcl[o * IL + c]), __ldg(&ls[c * NI + l]), acc);
        Elreg = __expf(2.f * acc);
    }

    // preload: Wcg half, inputs, consts
    for (int i = tid; i < OHALF * IL * NI; i += NTHREADS)
        sWcgH[i] = Wcg[(OHALF * r) * (IL * NI) + i];
    for (int i = tid; i < TT * DIN; i += NTHREADS) {
        int t = i / DIN, k = i - t * DIN;
        sInp[i] = (k < NI) ? __ldg(&local_inputs[(t * BB + b) * NI + k])
                           : __ldg(&global_inputs[(t * BB + b) * NS + (k - NI)]);
    }
    if (tid < NS) sgb[tid] = LAM * __ldg(&distmat[b * NS + tid]);
    __syncthreads();

    // xv for t=0
    if (tid < NI)        xv[tid] = __ldg(&la0[b * NI + tid]) * sInp[tid];
    else if (tid < DIN)  xv[tid] = __ldg(&ga0[b * NS + (tid - NI)]) * sInp[tid];

    // ---------- Eg precompute: this rank's 12 o's, 512 compute threads ----------
    {
        int og = tid >> 7;        // 0..3 valid for tid<512
        int s0 = tid & 127;
        float a00=0.f,a01=0.f,a10=0.f,a11=0.f,a20=0.f,a21=0.f;
        const float* gsb = global_states + (size_t)b * (NS * NI * IL);
        for (int c = 0; c < IL; c++) {
            __syncthreads();
            for (int i = tid; i < NS * NI; i += NTHREADS) {
                int s = i >> 5, j = i & 31;
                sGs[s * 33 + j] = gsb[c * (NS * NI) + i];
            }
            __syncthreads();
            if (tid < 512) {
                #pragma unroll 8
                for (int j = 0; j < NI; j++) {
                    float gA = sGs[s0 * 33 + j];
                    float gB = sGs[(s0 + 128) * 33 + j];
                    float w0 = sWcgH[((og*3+0) * IL + c) * NI + j];
                    float w1 = sWcgH[((og*3+1) * IL + c) * NI + j];
                    float w2 = sWcgH[((og*3+2) * IL + c) * NI + j];
                    a00 = fmaf(w0, gA, a00); a01 = fmaf(w0, gB, a01);
                    a10 = fmaf(w1, gA, a10); a11 = fmaf(w1, gB, a11);
                    a20 = fmaf(w2, gA, a20); a21 = fmaf(w2, gB, a21);
                }
            }
        }
        __syncthreads();
        if (tid < 512) {
            float b0 = __ldg(&bcg[OHALF*r + og*3+0]);
            float b1 = __ldg(&bcg[OHALF*r + og*3+1]);
            float b2 = __ldg(&bcg[OHALF*r + og*3+2]);
            Eg[(og*3+0)*NS + s0      ] = __expf(2.f * (a00 + b0));
            Eg[(og*3+0)*NS + s0 + 128] = __expf(2.f * (a01 + b0));
            Eg[(og*3+1)*NS + s0      ] = __expf(2.f * (a10 + b1));
            Eg[(og*3+1)*NS + s0 + 128] = __expf(2.f * (a11 + b1));
            Eg[(og*3+2)*NS + s0      ] = __expf(2.f * (a20 + b2));
            Eg[(og*3+2)*NS + s0 + 128] = __expf(2.f * (a21 + b2));
        }
    }
    __syncthreads();

    // steady-state: y-dot weight halves (this rank's h columns)
    for (int i = tid; i < VEC * 128; i += NTHREADS) {
        int d = i >> 7, hh = i & 127;
        sWll[i] = Wll[d * HH + 128 * r + hh];
        sWlg[i] = Wlg[d * HH + 128 * r + hh];
    }
    __syncthreads();

    // per-thread hoisted constants
    float Ereg[3];
    {
        int grp = tid >> 8, s = tid & 255;
        #pragma unroll
        for (int oi = 0; oi < 3; oi++) Ereg[oi] = Eg[(3 * grp + oi) * NS + s];
    }
    float biasreg = (tid < JJ) ? g_gbiasC[r * JJ + tid] : 0.f;
    float wlreg = 0.f, wgreg = 0.f, bllreg = 0.f, blgreg = 0.f;
    if (tid < VEC) {
        wlreg  = -2.f * __ldg(&vl[tid]);
        wgreg  = -2.f * (1.f - LAM) * __ldg(&vg[tid]);
        bllreg = __ldg(&bll[tid]);
        blgreg = __ldg(&blg[tid]);
    }

    float* out_h  = out;
    float* out_c  = out + TT * BB * HH;
    float* out_la = out_c + BB * HH;
    float* out_ga = out_la + TT * BB * NI;

    // all mbarriers initialized + smem ready in both CTAs
    cluster_sync_all();

    for (int t = 0; t < TT; t++) {
        const unsigned ph = (unsigned)(t & 1);

        // ---- gates: 768 threads, K-split x2, 18 LDG.128 each ----
        if (tid < 2 * JJ) {
            int khalf = tid >= JJ;
            int jj = tid - khalf * JJ;
            float a0 = khalf ? 0.f : biasreg, a1 = 0.f;
            const uint4* wp = g_W4c + (size_t)r * (KC * JJ) + jj;
            const float4* xv4 = (const float4*)xv;
            #pragma unroll 6
            for (int q = 0; q < 18; q++) {
                int kc = khalf * 18 + q;
                uint4 ww = wp[(size_t)kc * JJ];
                float4 xa = xv4[2 * kc], xb = xv4[2 * kc + 1];
                float2 f0 = __half22float2(*(__half2*)&ww.x);
                float2 f1 = __half22float2(*(__half2*)&ww.y);
                float2 f2 = __half22float2(*(__half2*)&ww.z);
                float2 f3 = __half22float2(*(__half2*)&ww.w);
                a0 = fmaf(xa.x, f0.x, a0); a1 = fmaf(xa.y, f0.y, a1);
                a0 = fmaf(xa.z, f1.x, a0); a1 = fmaf(xa.w, f1.y, a1);
                a0 = fmaf(xb.x, f2.x, a0); a1 = fmaf(xb.y, f2.y, a1);
                a0 = fmaf(xb.z, f3.x, a0); a1 = fmaf(xb.w, f3.y, a1);
            }
            garr[tid] = a0 + a1;
        }
        __syncthreads();   // B1

        // ---- LSTM: this rank's 128 h units ----
        if (tid < 128) {
            float ig = garr[tid]       + garr[JJ + tid];
            float gg = garr[128 + tid] + garr[JJ + 128 + tid];
            float og = garr[256 + tid] + garr[JJ + 256 + tid];
            float si = frcp(1.f + __expf(-ig));
            float tg = fmaf(-2.f, frcp(1.f + __expf(2.f * gg)), 1.f);
            float cval = si * tg;
            float so = frcp(1.f + __expf(-og));
            float tc = fmaf(-2.f, frcp(1.f + __expf(2.f * cval)), 1.f);
            cvl[tid] = cval;
            int hg = 128 * r + tid;
            out_h[(size_t)(t * BB + b) * HH + hg] = so * tc;
            if (t == TT - 1) out_c[(size_t)b * HH + hg] = cval;
        }
        __syncthreads();   // B2

        // ---- y partial dots over local c half; export to peer ----
        if (w < VEC) {
            float a = 0.f, bg = 0.f;
            const float* wr  = sWll + w * 128;
            const float* wr2 = sWlg + w * 128;
            #pragma unroll
            for (int i = 0; i < 4; i++) {
                float cc = cvl[lane + 32 * i];
                a  = fmaf(cc, wr[lane + 32 * i], a);
                bg = fmaf(cc, wr2[lane + 32 * i], bg);
            }
            #pragma unroll
            for (int off = 16; off; off >>= 1) {
                a  += __shfl_xor_sync(0xffffffffu, a, off);
                bg += __shfl_xor_sync(0xffffffffu, bg, off);
            }
            if (lane == 0) {
                ymine[w] = make_float2(a, bg);
                stc_b64(p_ypeer + (unsigned)(w * 8), a, bg);
                mbar_arrive_remote(p_barE1);
            }
        }
        __syncthreads();   // B3 (ymine visible CTA-wide)

        if (tid < VEC) {
            mbar_wait(barE1, ph);
            float2 m = ymine[tid], p = ypeer[tid];
            tvl[tid] = make_float2(__expf(2.f * (m.x + p.x + bllreg)), wlreg);
            tvg[tid] = make_float2(__expf(2.f * (m.y + p.y + blgreg)), wgreg);
        }
        __syncthreads();   // B4

        // ---- partials over this rank's 12 o's ----
        {
            float acc = 0.f;
            const float4* tq = (const float4*)tvg;
            #pragma unroll
            for (int dq = 0; dq < 6; dq++) {
                float4 A = tq[2*dq], B = tq[2*dq+1];
                #pragma unroll
                for (int oi = 0; oi < 3; oi++) {
                    float E = Ereg[oi];
                    float d1 = fmaf(E, A.x, 1.f), d2 = fmaf(E, A.z, 1.f);
                    float d3 = fmaf(E, B.x, 1.f), d4 = fmaf(E, B.z, 1.f);
                    float p12 = d1 * d2, p34 = d3 * d4;
                    float n12 = A.y * d2; n12 = fmaf(A.w, d1, n12);
                    float n34 = B.y * d4; n34 = fmaf(B.w, d3, n34);
                    float num = n12 * p34; num = fmaf(n34, p12, num);
                    acc = fmaf(num, frcp(p12 * p34), acc);
                }
            }
            psg[tid] = acc;
        }
        if (tid < OHALF * NI) {
            float acc = 0.f, E = Elreg;
            const float4* tq = (const float4*)tvl;
            #pragma unroll
            for (int dq = 0; dq < 6; dq++) {
                float4 A = tq[2*dq], B = tq[2*dq+1];
                float d1 = fmaf(E, A.x, 1.f), d2 = fmaf(E, A.z, 1.f);
                float d3 = fmaf(E, B.x, 1.f), d4 = fmaf(E, B.z, 1.f);
                float p12 = d1 * d2, p34 = d3 * d4;
                float n12 = A.y * d2; n12 = fmaf(A.w, d1, n12);
                float n34 = B.y * d4; n34 = fmaf(B.w, d3, n34);
                float num = n12 * p34; num = fmaf(n34, p12, num);
                acc = fmaf(num, frcp(p12 * p34), acc);
            }
            psl[tid] = acc;
        }
        __syncthreads();   // B5

        // ---- reduce local halves, export to peer (E2: 288 arrivals) ----
        float myg = 0.f, myl = 0.f;
        if (tid < NS) {
            myg = psg[tid] + psg[256 + tid] + psg[512 + tid] + psg[768 + tid];
            stc_f32(p_sgp + (unsigned)(tid * 4), myg);
            mbar_arrive_remote(p_barE2);
        } else if (tid < NS + NI) {
            int l = tid - NS;
            #pragma unroll
            for (int o = 0; o < OHALF; o++) myl += psl[o * NI + l];
            stc_f32(p_slp + (unsigned)(l * 4), myl);
            mbar_arrive_remote(p_barE2);
        }
        mbar_wait(barE2, ph);   // all threads

        // ---- combine + softmaxes ----
        float vreg = 0.f, ereg = 0.f;
        if (tid < NS) {
            vreg = myg + sgp[tid] + sgb[tid];
            float m = vreg;
            #pragma unroll
            for (int off = 16; off; off >>= 1) m = fmaxf(m, __shfl_xor_sync(0xffffffffu, m, off));
            if (lane == 0) red[w] = m;
        } else if (tid < NS + NI) {   // warp 8: full local softmax
            int l = tid - NS;
            float v = myl + slp[l];
            float m = v;
            #pragma unroll
            for (int off = 16; off; off >>= 1) m = fmaxf(m, __shfl_xor_sync(0xffffffffu, m, off));
            float e = __expf(v - m);
            float su = e;
            #pragma unroll
            for (int off = 16; off; off >>= 1) su += __shfl_xor_sync(0xffffffffu, su, off);
            float a = e * frcp(su);
            if (r == 1) out_la[(size_t)(t * BB + b) * NI + l] = a;
            if (t + 1 < TT) xv[l] = a * sInp[(t + 1) * DIN + l];
        }
        __syncthreads();   // B6

        if (tid < NS) {
            float m = fmaxf(fmaxf(fmaxf(red[0], red[1]), fmaxf(red[2], red[3])),
                            fmaxf(fmaxf(red[4], red[5]), fmaxf(red[6], red[7])));
            ereg = __expf(vreg - m);
            float su = ereg;
            #pragma unroll
            for (int off = 16; off; off >>= 1) su += __shfl_xor_sync(0xffffffffu, su, off);
            if (lane == 0) red[8 + w] = su;
        }
        __syncthreads();   // B7

        if (tid < NS) {
            float su = red[8] + red[9] + red[10] + red[11]
                     + red[12] + red[13] + red[14] + red[15];
            float a = ereg * frcp(su);
            if (r == 0) out_ga[(size_t)(t * BB + b) * NS + tid] = a;
            if (t + 1 < TT) xv[NI + tid] = a * sInp[(t + 1) * DIN + NI + tid];
        }
        __syncthreads();   // B8 (xv ready for next gates)
    }

    cluster_sync_all();
}

extern "C" void kernel_launch(void* const* d_in, const int* in_sizes, int n_in,
                              void* d_out, int out_size) {
    const float* local_inputs  = (const float*)d_in[0];
    const float* global_inputs = (const float*)d_in[1];
    const float* local_states  = (const float*)d_in[2];
    const float* global_states = (const float*)d_in[3];
    const float* distmat       = (const float*)d_in[4];
    const float* la0           = (const float*)d_in[5];
    const float* ga0           = (const float*)d_in[6];
    const float* Wcl = (const float*)d_in[7];
    const float* bcl = (const float*)d_in[8];
    const float* Wll = (const float*)d_in[9];
    const float* bll = (const float*)d_in[10];
    const float* vl  = (const float*)d_in[11];
    const float* Wcg = (const float*)d_in[12];
    const float* bcg = (const float*)d_in[13];
    const float* Wlg = (const float*)d_in[14];
    const float* blg = (const float*)d_in[15];
    const float* vg  = (const float*)d_in[16];
    const float* Wih = (const float*)d_in[17];
    const float* bih = (const float*)d_in[18];
    const float* bhh = (const float*)d_in[19];
    float* out = (float*)d_out;

    cudaFuncSetAttribute(spatial_attn_kernel,
                         cudaFuncAttributeMaxDynamicSharedMemorySize, SMEM_BYTES);

    prep_kernel<<<(2 * KC * JJ + 255) / 256, 256>>>(Wih, bih, bhh);
    spatial_attn_kernel<<<2 * BB, NTHREADS, SMEM_BYTES>>>(
        local_inputs, global_inputs, local_states, global_states, distmat,
        la0, ga0, Wcl, bcl, Wll, bll, vl, Wcg, bcg, Wlg, blg, vg, out);
}

// round 6
// speedup vs baseline: 2.4045x; 1.0085x over previous
#include <cuda_runtime.h>
#include <cuda_fp16.h>
#include <cstdint>
#include <math.h>

#define TT   24
#define BB   64
#define NI   32
#define IL   24
#define VEC  24
#define NS   256
#define HH   256
#define DIN  288
#define LAM  0.2f
#define NTHREADS 1024
#define KC   36        // DIN/8 chunks
#define JJ   384       // gate outputs per rank (i,g,o x 128)
#define OHALF 12       // o-range per rank

typedef unsigned long long ull;

// --------- device scratch ----------
__device__ uint4 g_W4c[2 * KC * JJ];   // [r][kc][jj]
__device__ float g_gbiasC[2 * JJ];

__device__ __forceinline__ float frcp(float x) {
    float y; asm("rcp.approx.f32 %0, %1;" : "=f"(y) : "f"(x)); return y;
}
// ---- packed f32x2 helpers ----
__device__ __forceinline__ ull pk2(float x, float y) {
    ull r; asm("mov.b64 %0, {%1,%2};" : "=l"(r) : "f"(x), "f"(y)); return r;
}
__device__ __forceinline__ ull pkdup(float x) { return pk2(x, x); }
__device__ __forceinline__ float2 upk(ull v) {
    float2 f; asm("mov.b64 {%0,%1}, %2;" : "=f"(f.x), "=f"(f.y) : "l"(v)); return f;
}
__device__ __forceinline__ ull fma2(ull a, ull b, ull c) {
    ull d; asm("fma.rn.f32x2 %0, %1, %2, %3;" : "=l"(d) : "l"(a), "l"(b), "l"(c)); return d;
}
__device__ __forceinline__ ull mul2(ull a, ull b) {
    ull d; asm("mul.rn.f32x2 %0, %1, %2;" : "=l"(d) : "l"(a), "l"(b)); return d;
}
__device__ __forceinline__ ull rcp2(ull v) {
    float2 f = upk(v); return pk2(frcp(f.x), frcp(f.y));
}

__device__ __forceinline__ unsigned s2u(const void* p) {
    unsigned a; asm("{ .reg .u64 t; cvta.to.shared.u64 t, %1; cvt.u32.u64 %0, t; }" : "=r"(a) : "l"(p)); return a;
}
__device__ __forceinline__ unsigned mapa_u32(unsigned a, unsigned r) {
    unsigned o; asm("mapa.shared::cluster.u32 %0, %1, %2;" : "=r"(o) : "r"(a), "r"(r)); return o;
}
__device__ __forceinline__ void stc_f32(unsigned a, float v) {
    asm volatile("st.shared::cluster.f32 [%0], %1;" :: "r"(a), "f"(v) : "memory");
}
__device__ __forceinline__ void stc_b64(unsigned a, float x, float y) {
    unsigned long long u; asm("mov.b64 %0, {%1,%2};" : "=l"(u) : "f"(x), "f"(y));
    asm volatile("st.shared::cluster.b64 [%0], %1;" :: "r"(a), "l"(u) : "memory");
}
__device__ __forceinline__ void mbar_init(unsigned a, unsigned c) {
    asm volatile("mbarrier.init.shared.b64 [%0], %1;" :: "r"(a), "r"(c) : "memory");
}
__device__ __forceinline__ void mbar_arrive_remote(unsigned a) {
    asm volatile("mbarrier.arrive.release.cluster.shared::cluster.b64 _, [%0];" :: "r"(a) : "memory");
}
__device__ __forceinline__ void mbar_wait(unsigned a, unsigned ph) {
    unsigned done;
    asm volatile("{ .reg .pred p; mbarrier.try_wait.parity.acquire.cluster.shared::cta.b64 p, [%1], %2; selp.b32 %0,1,0,p; }"
        : "=r"(done) : "r"(a), "r"(ph) : "memory");
    while (!done) {
        asm volatile("{ .reg .pred p; mbarrier.try_wait.parity.acquire.cluster.shared::cta.b64 p, [%1], %2, 0x989680; selp.b32 %0,1,0,p; }"
            : "=r"(done) : "r"(a), "r"(ph) : "memory");
    }
}
__device__ __forceinline__ unsigned ctarank() {
    unsigned r; asm("mov.u32 %0, %%cluster_ctarank;" : "=r"(r)); return r;
}
__device__ __forceinline__ void cluster_sync_all() {
    asm volatile("barrier.cluster.arrive.aligned;" ::: "memory");
    asm volatile("barrier.cluster.wait.aligned;" ::: "memory");
}

__global__ void prep_kernel(const float* __restrict__ Wih,
                            const float* __restrict__ bih,
                            const float* __restrict__ bhh) {
    int idx = blockIdx.x * blockDim.x + threadIdx.x;
    int total = 2 * KC * JJ;
    for (int i = idx; i < total; i += gridDim.x * blockDim.x) {
        int r  = i / (KC * JJ);
        int rem = i - r * (KC * JJ);
        int kc = rem / JJ, jj = rem - kc * JJ;
        int h = 128 * r + (jj & 127);
        int row = (jj < 128) ? h : (jj < 256) ? (512 + h) : (768 + h);
        const float* src = Wih + row * DIN + kc * 8;
        __half2 h0 = __floats2half2_rn(src[0], src[1]);
        __half2 h1 = __floats2half2_rn(src[2], src[3]);
        __half2 h2 = __floats2half2_rn(src[4], src[5]);
        __half2 h3 = __floats2half2_rn(src[6], src[7]);
        uint4 u;
        u.x = *(unsigned*)&h0; u.y = *(unsigned*)&h1;
        u.z = *(unsigned*)&h2; u.w = *(unsigned*)&h3;
        g_W4c[i] = u;
    }
    if (idx < 2 * JJ) {
        int r = idx / JJ, jj = idx - r * JJ;
        int h = 128 * r + (jj & 127);
        int row = (jj < 128) ? h : (jj < 256) ? (512 + h) : (768 + h);
        g_gbiasC[idx] = bih[row] + bhh[row];
    }
}

// ---------------- smem layout (floats) ----------------
#define A_OFF     0          // precompute: sWcgH(9216)+sGs(8448)=17664 ; steady: sWll(3072)+sWlg(3072)
#define A_SIZE    17664
#define EG_OFF    (A_OFF + A_SIZE)     // 3072
#define SINP_OFF  (EG_OFF + 3072)      // 6912
#define SGB_OFF   (SINP_OFF + 6912)    // 256
#define GARR_OFF  (SGB_OFF + 256)      // 768
#define XV_OFF    (GARR_OFF + 768)     // 288 (16B aligned)
#define CVL_OFF   (XV_OFF + 288)       // 128
#define YMINE_OFF (CVL_OFF + 128)      // 48 (float2[24])
#define YPEER_OFF (YMINE_OFF + 48)     // 48
#define TVL_OFF   (YPEER_OFF + 48)     // 48
#define TVG_OFF   (TVL_OFF + 48)       // 48
#define PSG_OFF   (TVG_OFF + 48)       // 3072 (float2[6][256])
#define PSL_OFF   (PSG_OFF + 3072)     // 384  (float2[6][32])
#define SGP_OFF   (PSL_OFF + 384)      // 256
#define SLP_OFF   (SGP_OFF + 256)      // 32
#define RED_OFF   (SLP_OFF + 32)       // 36
#define MBAR_OFF  (RED_OFF + 36)       // 4
#define SMEM_FLOATS (MBAR_OFF + 4)
#define SMEM_BYTES  (SMEM_FLOATS * 4)

__global__ __launch_bounds__(NTHREADS, 1) __cluster_dims__(2, 1, 1)
void spatial_attn_kernel(
    const float* __restrict__ local_inputs,
    const float* __restrict__ global_inputs,
    const float* __restrict__ local_states,
    const float* __restrict__ global_states,
    const float* __restrict__ distmat,
    const float* __restrict__ la0,
    const float* __restrict__ ga0,
    const float* __restrict__ Wcl, const float* __restrict__ bcl,
    const float* __restrict__ Wll, const float* __restrict__ bll,
    const float* __restrict__ vl,
    const float* __restrict__ Wcg, const float* __restrict__ bcg,
    const float* __restrict__ Wlg, const float* __restrict__ blg,
    const float* __restrict__ vg,
    float* __restrict__ out)
{
    extern __shared__ float sm[];
    float*  sWcgH = sm + A_OFF;
    float*  sGs   = sm + A_OFF + 9216;
    float*  sWll  = sm + A_OFF;
    float*  sWlg  = sm + A_OFF + 3072;
    float*  Eg    = sm + EG_OFF;           // [12][256]
    float*  sInp  = sm + SINP_OFF;
    float*  sgb   = sm + SGB_OFF;
    float*  garr  = sm + GARR_OFF;
    float*  xv    = sm + XV_OFF;
    float*  cvl   = sm + CVL_OFF;
    float2* ymine = (float2*)(sm + YMINE_OFF);
    float2* ypeer = (float2*)(sm + YPEER_OFF);
    float2* tvl   = (float2*)(sm + TVL_OFF);
    float2* tvg   = (float2*)(sm + TVG_OFF);
    float2* psgPk = (float2*)(sm + PSG_OFF);   // [pair<6][s<256]
    float2* pslPk = (float2*)(sm + PSL_OFF);   // [pair<6][l<32]
    float*  sgp   = sm + SGP_OFF;
    float*  slp   = sm + SLP_OFF;
    float*  red   = sm + RED_OFF;

    const int b   = blockIdx.x >> 1;
    const unsigned r = ctarank();
    const int tid = threadIdx.x;
    const int w = tid >> 5, lane = tid & 31;
    const ull one2 = 0x3F8000003F800000ULL;

    const unsigned barE1 = s2u(sm + MBAR_OFF);
    const unsigned barE2 = barE1 + 8;
    if (tid == 0) { mbar_init(barE1, 24); mbar_init(barE2, 288); }
    const unsigned peer = r ^ 1u;
    const unsigned p_ypeer = mapa_u32(s2u(sm + YPEER_OFF), peer);
    const unsigned p_sgp   = mapa_u32(s2u(sm + SGP_OFF), peer);
    const unsigned p_slp   = mapa_u32(s2u(sm + SLP_OFF), peer);
    const unsigned p_barE1 = mapa_u32(barE1, peer);
    const unsigned p_barE2 = mapa_u32(barE2, peer);

    // ---------- El (local conv): packed o-pairs held by threads 768..959 ----------
    ull Elpk = 0;
    if (tid >= 768 && tid < 960) {
        int idx = tid - 768;
        int p = idx >> 5, l = idx & 31;
        int o0 = OHALF * r + 2 * p;
        float acc0 = __ldg(&bcl[o0]), acc1 = __ldg(&bcl[o0 + 1]);
        const float* ls = local_states + b * (NI * IL);
        #pragma unroll
        for (int c = 0; c < IL; c++) {
            float sv = __ldg(&ls[c * NI + l]);
            acc0 = fmaf(__ldg(&Wcl[o0 * IL + c]),       sv, acc0);
            acc1 = fmaf(__ldg(&Wcl[(o0 + 1) * IL + c]), sv, acc1);
        }
        Elpk = pk2(__expf(2.f * acc0), __expf(2.f * acc1));
    }

    // preload: Wcg half, inputs, consts
    for (int i = tid; i < OHALF * IL * NI; i += NTHREADS)
        sWcgH[i] = Wcg[(OHALF * r) * (IL * NI) + i];
    for (int i = tid; i < TT * DIN; i += NTHREADS) {
        int t = i / DIN, k = i - t * DIN;
        sInp[i] = (k < NI) ? __ldg(&local_inputs[(t * BB + b) * NI + k])
                           : __ldg(&global_inputs[(t * BB + b) * NS + (k - NI)]);
    }
    if (tid < NS) sgb[tid] = LAM * __ldg(&distmat[b * NS + tid]);
    __syncthreads();

    // xv for t=0
    if (tid < NI)        xv[tid] = __ldg(&la0[b * NI + tid]) * sInp[tid];
    else if (tid < DIN)  xv[tid] = __ldg(&ga0[b * NS + (tid - NI)]) * sInp[tid];

    // ---------- Eg precompute: this rank's 12 o's ----------
    {
        int og = tid >> 7;        // 0..3 valid for tid<512
        int s0 = tid & 127;
        float a00=0.f,a01=0.f,a10=0.f,a11=0.f,a20=0.f,a21=0.f;
        const float* gsb = global_states + (size_t)b * (NS * NI * IL);
        for (int c = 0; c < IL; c++) {
            __syncthreads();
            for (int i = tid; i < NS * NI; i += NTHREADS) {
                int s = i >> 5, j = i & 31;
                sGs[s * 33 + j] = gsb[c * (NS * NI) + i];
            }
            __syncthreads();
            if (tid < 512) {
                #pragma unroll 8
                for (int j = 0; j < NI; j++) {
                    float gA = sGs[s0 * 33 + j];
                    float gB = sGs[(s0 + 128) * 33 + j];
                    float w0 = sWcgH[((og*3+0) * IL + c) * NI + j];
                    float w1 = sWcgH[((og*3+1) * IL + c) * NI + j];
                    float w2 = sWcgH[((og*3+2) * IL + c) * NI + j];
                    a00 = fmaf(w0, gA, a00); a01 = fmaf(w0, gB, a01);
                    a10 = fmaf(w1, gA, a10); a11 = fmaf(w1, gB, a11);
                    a20 = fmaf(w2, gA, a20); a21 = fmaf(w2, gB, a21);
                }
            }
        }
        __syncthreads();
        if (tid < 512) {
            float b0 = __ldg(&bcg[OHALF*r + og*3+0]);
            float b1 = __ldg(&bcg[OHALF*r + og*3+1]);
            float b2 = __ldg(&bcg[OHALF*r + og*3+2]);
            Eg[(og*3+0)*NS + s0      ] = __expf(2.f * (a00 + b0));
            Eg[(og*3+0)*NS + s0 + 128] = __expf(2.f * (a01 + b0));
            Eg[(og*3+1)*NS + s0      ] = __expf(2.f * (a10 + b1));
            Eg[(og*3+1)*NS + s0 + 128] = __expf(2.f * (a11 + b1));
            Eg[(og*3+2)*NS + s0      ] = __expf(2.f * (a20 + b2));
            Eg[(og*3+2)*NS + s0 + 128] = __expf(2.f * (a21 + b2));
        }
    }
    __syncthreads();

    // steady-state: y-dot weight halves
    for (int i = tid; i < VEC * 128; i += NTHREADS) {
        int d = i >> 7, hh = i & 127;
        sWll[i] = Wll[d * HH + 128 * r + hh];
        sWlg[i] = Wlg[d * HH + 128 * r + hh];
    }
    __syncthreads();

    // per-thread hoisted constants: packed E pairs
    const int grp = tid >> 8;       // 0..3
    const int sdx = tid & 255;
    ull Epk0 = 0, Epk1 = 0;
    if (grp < 3) {
        Epk0 = pk2(Eg[(4*grp + 0) * NS + sdx], Eg[(4*grp + 1) * NS + sdx]);
        Epk1 = pk2(Eg[(4*grp + 2) * NS + sdx], Eg[(4*grp + 3) * NS + sdx]);
    }
    float biasreg = (tid < JJ) ? g_gbiasC[r * JJ + tid] : 0.f;
    float wlreg = 0.f, wgreg = 0.f, bllreg = 0.f, blgreg = 0.f;
    if (tid < VEC) {
        wlreg  = -2.f * __ldg(&vl[tid]);
        wgreg  = -2.f * (1.f - LAM) * __ldg(&vg[tid]);
        bllreg = __ldg(&bll[tid]);
        blgreg = __ldg(&blg[tid]);
    }

    float* out_h  = out;
    float* out_c  = out + TT * BB * HH;
    float* out_la = out_c + BB * HH;
    float* out_ga = out_la + TT * BB * NI;

    cluster_sync_all();

    for (int t = 0; t < TT; t++) {
        const unsigned ph = (unsigned)(t & 1);

        // ---- gates: 768 threads, K-split x2 ----
        if (tid < 2 * JJ) {
            int khalf = tid >= JJ;
            int jj = tid - khalf * JJ;
            float a0 = khalf ? 0.f : biasreg, a1 = 0.f;
            const uint4* wp = g_W4c + (size_t)r * (KC * JJ) + jj;
            const float4* xv4 = (const float4*)xv;
            #pragma unroll 6
            for (int q = 0; q < 18; q++) {
                int kc = khalf * 18 + q;
                uint4 ww = wp[(size_t)kc * JJ];
                float4 xa = xv4[2 * kc], xb = xv4[2 * kc + 1];
                float2 f0 = __half22float2(*(__half2*)&ww.x);
                float2 f1 = __half22float2(*(__half2*)&ww.y);
                float2 f2 = __half22float2(*(__half2*)&ww.z);
                float2 f3 = __half22float2(*(__half2*)&ww.w);
                a0 = fmaf(xa.x, f0.x, a0); a1 = fmaf(xa.y, f0.y, a1);
                a0 = fmaf(xa.z, f1.x, a0); a1 = fmaf(xa.w, f1.y, a1);
                a0 = fmaf(xb.x, f2.x, a0); a1 = fmaf(xb.y, f2.y, a1);
                a0 = fmaf(xb.z, f3.x, a0); a1 = fmaf(xb.w, f3.y, a1);
            }
            garr[tid] = a0 + a1;
        }
        __syncthreads();   // B1

        // ---- LSTM: this rank's 128 h units ----
        if (tid < 128) {
            float ig = garr[tid]       + garr[JJ + tid];
            float gg = garr[128 + tid] + garr[JJ + 128 + tid];
            float og = garr[256 + tid] + garr[JJ + 256 + tid];
            float si = frcp(1.f + __expf(-ig));
            float tg = fmaf(-2.f, frcp(1.f + __expf(2.f * gg)), 1.f);
            float cval = si * tg;
            float so = frcp(1.f + __expf(-og));
            float tc = fmaf(-2.f, frcp(1.f + __expf(2.f * cval)), 1.f);
            cvl[tid] = cval;
            int hg = 128 * r + tid;
            out_h[(size_t)(t * BB + b) * HH + hg] = so * tc;
            if (t == TT - 1) out_c[(size_t)b * HH + hg] = cval;
        }
        __syncthreads();   // B2

        // ---- y partial dots over local c half; export to peer ----
        if (w < VEC) {
            float a = 0.f, bg = 0.f;
            const float* wr  = sWll + w * 128;
            const float* wr2 = sWlg + w * 128;
            #pragma unroll
            for (int i = 0; i < 4; i++) {
                float cc = cvl[lane + 32 * i];
                a  = fmaf(cc, wr[lane + 32 * i], a);
                bg = fmaf(cc, wr2[lane + 32 * i], bg);
            }
            #pragma unroll
            for (int off = 16; off; off >>= 1) {
                a  += __shfl_xor_sync(0xffffffffu, a, off);
                bg += __shfl_xor_sync(0xffffffffu, bg, off);
            }
            if (lane == 0) {
                ymine[w] = make_float2(a, bg);
                stc_b64(p_ypeer + (unsigned)(w * 8), a, bg);
                mbar_arrive_remote(p_barE1);
            }
        }
        __syncthreads();   // B3

        if (tid < VEC) {
            mbar_wait(barE1, ph);
            float2 m = ymine[tid], p = ypeer[tid];
            tvl[tid] = make_float2(__expf(2.f * (m.x + p.x + bllreg)), wlreg);
            tvg[tid] = make_float2(__expf(2.f * (m.y + p.y + blgreg)), wgreg);
        }
        __syncthreads();   // B4

        // ---- partials: packed f32x2, o-pairs ----
        if (grp < 3) {
            ull acc0 = 0, acc1 = 0;
            #pragma unroll
            for (int dq = 0; dq < 6; dq++) {
                float2 t0 = tvg[4*dq+0], t1 = tvg[4*dq+1];
                float2 t2 = tvg[4*dq+2], t3 = tvg[4*dq+3];
                ull F1 = pkdup(t0.x), W1 = pkdup(t0.y);
                ull F2 = pkdup(t1.x), W2 = pkdup(t1.y);
                ull F3 = pkdup(t2.x), W3 = pkdup(t2.y);
                ull F4 = pkdup(t3.x), W4 = pkdup(t3.y);
                {
                    ull D1 = fma2(Epk0, F1, one2), D2 = fma2(Epk0, F2, one2);
                    ull D3 = fma2(Epk0, F3, one2), D4 = fma2(Epk0, F4, one2);
                    ull p12 = mul2(D1, D2), p34 = mul2(D3, D4);
                    ull n12 = fma2(W2, D1, mul2(W1, D2));
                    ull n34 = fma2(W4, D3, mul2(W3, D4));
                    ull num = fma2(n34, p12, mul2(n12, p34));
                    acc0 = fma2(num, rcp2(mul2(p12, p34)), acc0);
                }
                {
                    ull D1 = fma2(Epk1, F1, one2), D2 = fma2(Epk1, F2, one2);
                    ull D3 = fma2(Epk1, F3, one2), D4 = fma2(Epk1, F4, one2);
                    ull p12 = mul2(D1, D2), p34 = mul2(D3, D4);
                    ull n12 = fma2(W2, D1, mul2(W1, D2));
                    ull n34 = fma2(W4, D3, mul2(W3, D4));
                    ull num = fma2(n34, p12, mul2(n12, p34));
                    acc1 = fma2(num, rcp2(mul2(p12, p34)), acc1);
                }
            }
            psgPk[(2*grp)     * NS + sdx] = upk(acc0);
            psgPk[(2*grp + 1) * NS + sdx] = upk(acc1);
        } else if (tid < 960) {   // threads 768..959: local partials, packed o-pairs
            int idx = tid - 768;  // = p*32 + l
            ull acc = 0;
            #pragma unroll
            for (int dq = 0; dq < 6; dq++) {
                float2 t0 = tvl[4*dq+0], t1 = tvl[4*dq+1];
                float2 t2 = tvl[4*dq+2], t3 = tvl[4*dq+3];
                ull F1 = pkdup(t0.x), W1 = pkdup(t0.y);
                ull F2 = pkdup(t1.x), W2 = pkdup(t1.y);
                ull F3 = pkdup(t2.x), W3 = pkdup(t2.y);
                ull F4 = pkdup(t3.x), W4 = pkdup(t3.y);
                ull D1 = fma2(Elpk, F1, one2), D2 = fma2(Elpk, F2, one2);
                ull D3 = fma2(Elpk, F3, one2), D4 = fma2(Elpk, F4, one2);
                ull p12 = mul2(D1, D2), p34 = mul2(D3, D4);
                ull n12 = fma2(W2, D1, mul2(W1, D2));
                ull n34 = fma2(W4, D3, mul2(W3, D4));
                ull num = fma2(n34, p12, mul2(n12, p34));
                acc = fma2(num, rcp2(mul2(p12, p34)), acc);
            }
            pslPk[idx] = upk(acc);
        }
        __syncthreads();   // B5

        // ---- reduce local halves, export to peer (E2: 288 arrivals) ----
        float myg = 0.f, myl = 0.f;
        if (tid < NS) {
            #pragma unroll
            for (int p = 0; p < 6; p++) {
                float2 v = psgPk[p * NS + tid];
                myg += v.x + v.y;
            }
            stc_f32(p_sgp + (unsigned)(tid * 4), myg);
            mbar_arrive_remote(p_barE2);
        } else if (tid < NS + NI) {
            int l = tid - NS;
            #pragma unroll
            for (int p = 0; p < 6; p++) {
                float2 v = pslPk[p * NI + l];
                myl += v.x + v.y;
            }
            stc_f32(p_slp + (unsigned)(l * 4), myl);
            mbar_arrive_remote(p_barE2);
        }
        mbar_wait(barE2, ph);

        // ---- combine + softmaxes ----
        float vreg = 0.f, ereg = 0.f;
        if (tid < NS) {
            vreg = myg + sgp[tid] + sgb[tid];
            float m = vreg;
            #pragma unroll
            for (int off = 16; off; off >>= 1) m = fmaxf(m, __shfl_xor_sync(0xffffffffu, m, off));
            if (lane == 0) red[w] = m;
        } else if (tid < NS + NI) {
            int l = tid - NS;
            float v = myl + slp[l];
            float m = v;
            #pragma unroll
            for (int off = 16; off; off >>= 1) m = fmaxf(m, __shfl_xor_sync(0xffffffffu, m, off));
            float e = __expf(v - m);
            float su = e;
            #pragma unroll
            for (int off = 16; off; off >>= 1) su += __shfl_xor_sync(0xffffffffu, su, off);
            float a = e * frcp(su);
            if (r == 1) out_la[(size_t)(t * BB + b) * NI + l] = a;
            if (t + 1 < TT) xv[l] = a * sInp[(t + 1) * DIN + l];
        }
        __syncthreads();   // B6

        if (tid < NS) {
            float m = fmaxf(fmaxf(fmaxf(red[0], red[1]), fmaxf(red[2], red[3])),
                            fmaxf(fmaxf(red[4], red[5]), fmaxf(red[6], red[7])));
            ereg = __expf(vreg - m);
            float su = ereg;
            #pragma unroll
            for (int off = 16; off; off >>= 1) su += __shfl_xor_sync(0xffffffffu, su, off);
            if (lane == 0) red[8 + w] = su;
        }
        __syncthreads();   // B7

        if (tid < NS) {
            float su = red[8] + red[9] + red[10] + red[11]
                     + red[12] + red[13] + red[14] + red[15];
            float a = ereg * frcp(su);
            if (r == 0) out_ga[(size_t)(t * BB + b) * NS + tid] = a;
            if (t + 1 < TT) xv[NI + tid] = a * sInp[(t + 1) * DIN + NI + tid];
        }
        __syncthreads();   // B8
    }

    cluster_sync_all();
}

extern "C" void kernel_launch(void* const* d_in, const int* in_sizes, int n_in,
                              void* d_out, int out_size) {
    const float* local_inputs  = (const float*)d_in[0];
    const float* global_inputs = (const float*)d_in[1];
    const float* local_states  = (const float*)d_in[2];
    const float* global_states = (const float*)d_in[3];
    const float* distmat       = (const float*)d_in[4];
    const float* la0           = (const float*)d_in[5];
    const float* ga0           = (const float*)d_in[6];
    const float* Wcl = (const float*)d_in[7];
    const float* bcl = (const float*)d_in[8];
    const float* Wll = (const float*)d_in[9];
    const float* bll = (const float*)d_in[10];
    const float* vl  = (const float*)d_in[11];
    const float* Wcg = (const float*)d_in[12];
    const float* bcg = (const float*)d_in[13];
    const float* Wlg = (const float*)d_in[14];
    const float* blg = (const float*)d_in[15];
    const float* vg  = (const float*)d_in[16];
    const float* Wih = (const float*)d_in[17];
    const float* bih = (const float*)d_in[18];
    const float* bhh = (const float*)d_in[19];
    float* out = (float*)d_out;

    cudaFuncSetAttribute(spatial_attn_kernel,
                         cudaFuncAttributeMaxDynamicSharedMemorySize, SMEM_BYTES);

    prep_kernel<<<(2 * KC * JJ + 255) / 256, 256>>>(Wih, bih, bhh);
    spatial_attn_kernel<<<2 * BB, NTHREADS, SMEM_BYTES>>>(
        local_inputs, global_inputs, local_states, global_states, distmat,
        la0, ga0, Wcl, bcl, Wll, bll, vl, Wcg, bcg, Wlg, blg, vg, out);
}

// round 7
// speedup vs baseline: 2.4488x; 1.0184x over previous
#include <cuda_runtime.h>
#include <cuda_fp16.h>
#include <cstdint>
#include <math.h>

#define TT   24
#define BB   64
#define NI   32
#define IL   24
#define VEC  24
#define NS   256
#define HH   256
#define DIN  288
#define LAM  0.2f
#define NTHREADS 1024
#define KC   36
#define JJ   384
#define OHALF 12
#define NCACHE 22      // kc-chunks cached in smem (kc 0..10 and 18..28)

typedef unsigned long long ull;

__device__ uint4 g_W4c[2 * KC * JJ];
__device__ float g_gbiasC[2 * JJ];

__device__ __forceinline__ float frcp(float x) {
    float y; asm("rcp.approx.f32 %0, %1;" : "=f"(y) : "f"(x)); return y;
}
__device__ __forceinline__ ull pk2(float x, float y) {
    ull r; asm("mov.b64 %0, {%1,%2};" : "=l"(r) : "f"(x), "f"(y)); return r;
}
__device__ __forceinline__ ull pkdup(float x) { return pk2(x, x); }
__device__ __forceinline__ float2 upk(ull v) {
    float2 f; asm("mov.b64 {%0,%1}, %2;" : "=f"(f.x), "=f"(f.y) : "l"(v)); return f;
}
__device__ __forceinline__ ull fma2(ull a, ull b, ull c) {
    ull d; asm("fma.rn.f32x2 %0, %1, %2, %3;" : "=l"(d) : "l"(a), "l"(b), "l"(c)); return d;
}
__device__ __forceinline__ ull mul2(ull a, ull b) {
    ull d; asm("mul.rn.f32x2 %0, %1, %2;" : "=l"(d) : "l"(a), "l"(b)); return d;
}
__device__ __forceinline__ ull rcp2(ull v) {
    float2 f = upk(v); return pk2(frcp(f.x), frcp(f.y));
}
__device__ __forceinline__ unsigned s2u(const void* p) {
    unsigned a; asm("{ .reg .u64 t; cvta.to.shared.u64 t, %1; cvt.u32.u64 %0, t; }" : "=r"(a) : "l"(p)); return a;
}
__device__ __forceinline__ unsigned mapa_u32(unsigned a, unsigned r) {
    unsigned o; asm("mapa.shared::cluster.u32 %0, %1, %2;" : "=r"(o) : "r"(a), "r"(r)); return o;
}
__device__ __forceinline__ void stc_f32(unsigned a, float v) {
    asm volatile("st.shared::cluster.f32 [%0], %1;" :: "r"(a), "f"(v) : "memory");
}
__device__ __forceinline__ void stc_b64(unsigned a, float x, float y) {
    ull u; asm("mov.b64 %0, {%1,%2};" : "=l"(u) : "f"(x), "f"(y));
    asm volatile("st.shared::cluster.b64 [%0], %1;" :: "r"(a), "l"(u) : "memory");
}
__device__ __forceinline__ void mbar_init(unsigned a, unsigned c) {
    asm volatile("mbarrier.init.shared.b64 [%0], %1;" :: "r"(a), "r"(c) : "memory");
}
__device__ __forceinline__ void mbar_arrive_remote(unsigned a) {
    asm volatile("mbarrier.arrive.release.cluster.shared::cluster.b64 _, [%0];" :: "r"(a) : "memory");
}
__device__ __forceinline__ void mbar_wait(unsigned a, unsigned ph) {
    unsigned done;
    asm volatile("{ .reg .pred p; mbarrier.try_wait.parity.acquire.cluster.shared::cta.b64 p, [%1], %2; selp.b32 %0,1,0,p; }"
        : "=r"(done) : "r"(a), "r"(ph) : "memory");
    while (!done) {
        asm volatile("{ .reg .pred p; mbarrier.try_wait.parity.acquire.cluster.shared::cta.b64 p, [%1], %2, 0x989680; selp.b32 %0,1,0,p; }"
            : "=r"(done) : "r"(a), "r"(ph) : "memory");
    }
}
__device__ __forceinline__ unsigned ctarank() {
    unsigned r; asm("mov.u32 %0, %%cluster_ctarank;" : "=r"(r)); return r;
}
__device__ __forceinline__ void cluster_sync_all() {
    asm volatile("barrier.cluster.arrive.aligned;" ::: "memory");
    asm volatile("barrier.cluster.wait.aligned;" ::: "memory");
}

__global__ void prep_kernel(const float* __restrict__ Wih,
                            const float* __restrict__ bih,
                            const float* __restrict__ bhh) {
    int idx = blockIdx.x * blockDim.x + threadIdx.x;
    int total = 2 * KC * JJ;
    for (int i = idx; i < total; i += gridDim.x * blockDim.x) {
        int r  = i / (KC * JJ);
        int rem = i - r * (KC * JJ);
        int kc = rem / JJ, jj = rem - kc * JJ;
        int h = 128 * r + (jj & 127);
        int row = (jj < 128) ? h : (jj < 256) ? (512 + h) : (768 + h);
        const float* src = Wih + row * DIN + kc * 8;
        __half2 h0 = __floats2half2_rn(src[0], src[1]);
        __half2 h1 = __floats2half2_rn(src[2], src[3]);
        __half2 h2 = __floats2half2_rn(src[4], src[5]);
        __half2 h3 = __floats2half2_rn(src[6], src[7]);
        uint4 u;
        u.x = *(unsigned*)&h0; u.y = *(unsigned*)&h1;
        u.z = *(unsigned*)&h2; u.w = *(unsigned*)&h3;
        g_W4c[i] = u;
    }
    if (idx < 2 * JJ) {
        int r = idx / JJ, jj = idx - r * JJ;
        int h = 128 * r + (jj & 127);
        int row = (jj < 128) ? h : (jj < 256) ? (512 + h) : (768 + h);
        g_gbiasC[idx] = bih[row] + bhh[row];
    }
}

// ---------------- smem layout (floats) ----------------
#define SWLL_OFF  0                       // 3072
#define SWLG_OFF  (SWLL_OFF + 3072)       // 3072
#define SINP_OFF  (SWLG_OFF + 3072)       // 6912
#define SGB_OFF   (SINP_OFF + 6912)       // 256
#define GARR_OFF  (SGB_OFF + 256)         // 768
#define XV_OFF    (GARR_OFF + 768)        // 288 (16B aligned)
#define CVL_OFF   (XV_OFF + 288)          // 128
#define TVL_OFF   (CVL_OFF + 128)         // 48
#define TVG_OFF   (TVL_OFF + 48)          // 48
#define PSG_OFF   (TVG_OFF + 48)          // 768 (float[3][256])
#define PSL_OFF   (PSG_OFF + 768)         // 192 (float[6][32])
#define SGP_OFF   (PSL_OFF + 192)         // 256
#define SLP_OFF   (SGP_OFF + 256)         // 32
#define RED_OFF   (SLP_OFF + 32)          // 16
#define MBAR_OFF  (RED_OFF + 16)          // 4 (two 8B mbarriers)
#define WC_OFF    (MBAR_OFF + 4)          // weight cache 22*384*4 = 33792
#define SMEM_FLOATS (WC_OFF + NCACHE * JJ * 4)
#define SMEM_BYTES  (SMEM_FLOATS * 4)

__global__ __launch_bounds__(NTHREADS, 1) __cluster_dims__(2, 1, 1)
void spatial_attn_kernel(
    const float* __restrict__ local_inputs,
    const float* __restrict__ global_inputs,
    const float* __restrict__ local_states,
    const float* __restrict__ global_states,
    const float* __restrict__ distmat,
    const float* __restrict__ la0,
    const float* __restrict__ ga0,
    const float* __restrict__ Wcl, const float* __restrict__ bcl,
    const float* __restrict__ Wll, const float* __restrict__ bll,
    const float* __restrict__ vl,
    const float* __restrict__ Wcg, const float* __restrict__ bcg,
    const float* __restrict__ Wlg, const float* __restrict__ blg,
    const float* __restrict__ vg,
    float* __restrict__ out)
{
    extern __shared__ float sm[];
    float*  sWll  = sm + SWLL_OFF;
    float*  sWlg  = sm + SWLG_OFF;
    float*  sInp  = sm + SINP_OFF;
    float*  sgb   = sm + SGB_OFF;
    float*  garr  = sm + GARR_OFF;
    float*  xv    = sm + XV_OFF;
    float*  cvl   = sm + CVL_OFF;
    float2* tvl   = (float2*)(sm + TVL_OFF);
    float2* tvg   = (float2*)(sm + TVG_OFF);
    float*  psg   = sm + PSG_OFF;
    float*  psl   = sm + PSL_OFF;
    float*  sgp   = sm + SGP_OFF;
    float*  slp   = sm + SLP_OFF;
    float*  red   = sm + RED_OFF;
    uint4*  sWcU4 = (uint4*)(sm + WC_OFF);
    // precompute overlays (inside weight-cache region, dead afterward)
    float*  sWcgH = sm + WC_OFF;            // 9216
    float*  sGs   = sm + WC_OFF + 9216;     // 8448
    float*  EgP   = sm + WC_OFF + 17664;    // 3072

    const int b   = blockIdx.x >> 1;
    const unsigned r = ctarank();
    const int tid = threadIdx.x;
    const int w = tid >> 5, lane = tid & 31;
    const ull one2 = 0x3F8000003F800000ULL;

    const unsigned barE1 = s2u(sm + MBAR_OFF);
    const unsigned barE2 = barE1 + 8;
    if (tid == 0) { mbar_init(barE1, 24); mbar_init(barE2, 288); }
    const unsigned peer = r ^ 1u;
    const unsigned p_ypeer = mapa_u32(s2u(sm + SGP_OFF), peer);   // reuse sgp region pre-partials? NO — separate below
    // dedicated ypeer region: reuse slp+red would clash; use a small dedicated buffer:
    // place ypeer in the first 48 floats of the weight cache? It's persistent... instead use psl region
    // (psl written later in the same step, AFTER tv consumed) -> hazard-free? psl written in partials
    // phase which is after tv read. But ypeer must survive until tv computed (before partials). Safe:
    // ypeer lives in psl[0..47] interval [ydot, tv-compute]; psl written after B3. OK.
    const unsigned p_ypeer2 = mapa_u32(s2u(sm + PSL_OFF), peer);
    const unsigned p_sgp   = mapa_u32(s2u(sm + SGP_OFF), peer);
    const unsigned p_slp   = mapa_u32(s2u(sm + SLP_OFF), peer);
    const unsigned p_barE1 = mapa_u32(barE1, peer);
    const unsigned p_barE2 = mapa_u32(barE2, peer);
    float2* ypeer = (float2*)(sm + PSL_OFF);

    // ---------- El (local conv): packed o-pairs, threads 768..959 ----------
    ull Elpk = 0;
    if (tid >= 768 && tid < 960) {
        int idx = tid - 768;
        int p = idx >> 5, l = idx & 31;
        int o0 = OHALF * r + 2 * p;
        float acc0 = __ldg(&bcl[o0]), acc1 = __ldg(&bcl[o0 + 1]);
        const float* ls = local_states + b * (NI * IL);
        #pragma unroll
        for (int c = 0; c < IL; c++) {
            float sv = __ldg(&ls[c * NI + l]);
            acc0 = fmaf(__ldg(&Wcl[o0 * IL + c]),       sv, acc0);
            acc1 = fmaf(__ldg(&Wcl[(o0 + 1) * IL + c]), sv, acc1);
        }
        Elpk = pk2(__expf(2.f * acc0), __expf(2.f * acc1));
    }

    // preload overlays + persistent small data
    for (int i = tid; i < OHALF * IL * NI; i += NTHREADS)
        sWcgH[i] = Wcg[(OHALF * r) * (IL * NI) + i];
    for (int i = tid; i < TT * DIN; i += NTHREADS) {
        int t = i / DIN, k = i - t * DIN;
        sInp[i] = (k < NI) ? __ldg(&local_inputs[(t * BB + b) * NI + k])
                           : __ldg(&global_inputs[(t * BB + b) * NS + (k - NI)]);
    }
    if (tid < NS) sgb[tid] = LAM * __ldg(&distmat[b * NS + tid]);
    for (int i = tid; i < VEC * 128; i += NTHREADS) {
        int d = i >> 7, hh = i & 127;
        sWll[i] = Wll[d * HH + 128 * r + hh];
        sWlg[i] = Wlg[d * HH + 128 * r + hh];
    }
    __syncthreads();

    // xv for t=0
    if (tid < NI)        xv[tid] = __ldg(&la0[b * NI + tid]) * sInp[tid];
    else if (tid < DIN)  xv[tid] = __ldg(&ga0[b * NS + (tid - NI)]) * sInp[tid];

    // ---------- Eg precompute ----------
    {
        int og = tid >> 7;        // valid for tid<512
        int s0 = tid & 127;
        float a00=0.f,a01=0.f,a10=0.f,a11=0.f,a20=0.f,a21=0.f;
        const float* gsb = global_states + (size_t)b * (NS * NI * IL);
        for (int c = 0; c < IL; c++) {
            __syncthreads();
            for (int i = tid; i < NS * NI; i += NTHREADS) {
                int s = i >> 5, j = i & 31;
                sGs[s * 33 + j] = gsb[c * (NS * NI) + i];
            }
            __syncthreads();
            if (tid < 512) {
                #pragma unroll 8
                for (int j = 0; j < NI; j++) {
                    float gA = sGs[s0 * 33 + j];
                    float gB = sGs[(s0 + 128) * 33 + j];
                    float w0 = sWcgH[((og*3+0) * IL + c) * NI + j];
                    float w1 = sWcgH[((og*3+1) * IL + c) * NI + j];
                    float w2 = sWcgH[((og*3+2) * IL + c) * NI + j];
                    a00 = fmaf(w0, gA, a00); a01 = fmaf(w0, gB, a01);
                    a10 = fmaf(w1, gA, a10); a11 = fmaf(w1, gB, a11);
                    a20 = fmaf(w2, gA, a20); a21 = fmaf(w2, gB, a21);
                }
            }
        }
        __syncthreads();
        if (tid < 512) {
            float b0 = __ldg(&bcg[OHALF*r + og*3+0]);
            float b1 = __ldg(&bcg[OHALF*r + og*3+1]);
            float b2 = __ldg(&bcg[OHALF*r + og*3+2]);
            EgP[(og*3+0)*NS + s0      ] = __expf(2.f * (a00 + b0));
            EgP[(og*3+0)*NS + s0 + 128] = __expf(2.f * (a01 + b0));
            EgP[(og*3+1)*NS + s0      ] = __expf(2.f * (a10 + b1));
            EgP[(og*3+1)*NS + s0 + 128] = __expf(2.f * (a11 + b1));
            EgP[(og*3+2)*NS + s0      ] = __expf(2.f * (a20 + b2));
            EgP[(og*3+2)*NS + s0 + 128] = __expf(2.f * (a21 + b2));
        }
    }
    __syncthreads();

    // hoist Eg into registers, then the overlays are dead
    const int grp = tid >> 8;       // 0..3
    const int sdx = tid & 255;
    ull Epk0 = 0, Epk1 = 0;
    if (grp < 3) {
        Epk0 = pk2(EgP[(4*grp + 0) * NS + sdx], EgP[(4*grp + 1) * NS + sdx]);
        Epk1 = pk2(EgP[(4*grp + 2) * NS + sdx], EgP[(4*grp + 3) * NS + sdx]);
    }
    __syncthreads();   // all Eg reads done before cache fill overwrites

    // ---------- fill smem weight cache: kc 0..10 -> slot 0..10, kc 18..28 -> slot 11..21 ----------
    {
        const uint4* src = g_W4c + (size_t)r * (KC * JJ);
        for (int i = tid; i < NCACHE * JJ; i += NTHREADS) {
            int slot = i / JJ, jj = i - slot * JJ;
            int kc = (slot < 11) ? slot : (slot + 7);
            sWcU4[i] = src[kc * JJ + jj];
        }
    }
    __syncthreads();

    float biasreg = (tid < JJ) ? g_gbiasC[r * JJ + tid] : 0.f;
    float wlreg = 0.f, wgreg = 0.f, bllreg = 0.f, blgreg = 0.f;
    if (lane == 0 && w < VEC) {
        wlreg  = -2.f * __ldg(&vl[w]);
        wgreg  = -2.f * (1.f - LAM) * __ldg(&vg[w]);
        bllreg = __ldg(&bll[w]);
        blgreg = __ldg(&blg[w]);
    }

    float* out_h  = out;
    float* out_c  = out + TT * BB * HH;
    float* out_la = out_c + BB * HH;
    float* out_ga = out_la + TT * BB * NI;

    cluster_sync_all();

    for (int t = 0; t < TT; t++) {
        const unsigned ph = (unsigned)(t & 1);

        // ---- gates: 768 threads, K-split x2; 11 LDS + 7 LDG per thread ----
        if (tid < 2 * JJ) {
            int khalf = tid >= JJ;
            int jj = tid - khalf * JJ;
            float a0 = khalf ? 0.f : biasreg, a1 = 0.f;
            const uint4* wg = g_W4c + (size_t)r * (KC * JJ) + jj;
            const uint4* ws = sWcU4 + (khalf * 11) * JJ + jj;
            const float4* xv4 = (const float4*)xv;
            #pragma unroll
            for (int q = 11; q < 18; q++) {       // gmem part first (MLP)
                int kc = khalf * 18 + q;
                uint4 ww = wg[(size_t)kc * JJ];
                float4 xa = xv4[2 * kc], xb = xv4[2 * kc + 1];
                float2 f0 = __half22float2(*(__half2*)&ww.x);
                float2 f1 = __half22float2(*(__half2*)&ww.y);
                float2 f2 = __half22float2(*(__half2*)&ww.z);
                float2 f3 = __half22float2(*(__half2*)&ww.w);
                a0 = fmaf(xa.x, f0.x, a0); a1 = fmaf(xa.y, f0.y, a1);
                a0 = fmaf(xa.z, f1.x, a0); a1 = fmaf(xa.w, f1.y, a1);
                a0 = fmaf(xb.x, f2.x, a0); a1 = fmaf(xb.y, f2.y, a1);
                a0 = fmaf(xb.z, f3.x, a0); a1 = fmaf(xb.w, f3.y, a1);
            }
            #pragma unroll
            for (int q = 0; q < 11; q++) {        // smem part
                int kc = khalf * 18 + q;
                uint4 ww = ws[q * JJ];
                float4 xa = xv4[2 * kc], xb = xv4[2 * kc + 1];
                float2 f0 = __half22float2(*(__half2*)&ww.x);
                float2 f1 = __half22float2(*(__half2*)&ww.y);
                float2 f2 = __half22float2(*(__half2*)&ww.z);
                float2 f3 = __half22float2(*(__half2*)&ww.w);
                a0 = fmaf(xa.x, f0.x, a0); a1 = fmaf(xa.y, f0.y, a1);
                a0 = fmaf(xa.z, f1.x, a0); a1 = fmaf(xa.w, f1.y, a1);
                a0 = fmaf(xb.x, f2.x, a0); a1 = fmaf(xb.y, f2.y, a1);
                a0 = fmaf(xb.z, f3.x, a0); a1 = fmaf(xb.w, f3.y, a1);
            }
            garr[tid] = a0 + a1;
        }
        __syncthreads();   // B1

        // ---- LSTM: critical path (0-127) + outputs (896-1023) ----
        if (tid < 128) {
            float ig = garr[tid]       + garr[JJ + tid];
            float gg = garr[128 + tid] + garr[JJ + 128 + tid];
            float si = frcp(1.f + __expf(-ig));
            float tg = fmaf(-2.f, frcp(1.f + __expf(2.f * gg)), 1.f);
            cvl[tid] = si * tg;
        } else if (tid >= 896) {
            int hid = tid - 896;
            float ig = garr[hid]       + garr[JJ + hid];
            float gg = garr[128 + hid] + garr[JJ + 128 + hid];
            float og = garr[256 + hid] + garr[JJ + 256 + hid];
            float si = frcp(1.f + __expf(-ig));
            float tg = fmaf(-2.f, frcp(1.f + __expf(2.f * gg)), 1.f);
            float cval = si * tg;
            float so = frcp(1.f + __expf(-og));
            float tc = fmaf(-2.f, frcp(1.f + __expf(2.f * cval)), 1.f);
            int hg = 128 * r + hid;
            out_h[(size_t)(t * BB + b) * HH + hg] = so * tc;
            if (t == TT - 1) out_c[(size_t)b * HH + hg] = cval;
        }
        __syncthreads();   // B2

        // ---- y dots (c-half) + E1 exchange + tv, all inside the owning warp ----
        if (w < VEC) {
            float a = 0.f, bg = 0.f;
            const float* wr  = sWll + w * 128;
            const float* wr2 = sWlg + w * 128;
            #pragma unroll
            for (int i = 0; i < 4; i++) {
                float cc = cvl[lane + 32 * i];
                a  = fmaf(cc, wr[lane + 32 * i], a);
                bg = fmaf(cc, wr2[lane + 32 * i], bg);
            }
            #pragma unroll
            for (int off = 16; off; off >>= 1) {
                a  += __shfl_xor_sync(0xffffffffu, a, off);
                bg += __shfl_xor_sync(0xffffffffu, bg, off);
            }
            if (lane == 0) {
                stc_b64(p_ypeer2 + (unsigned)(w * 8), a, bg);
                mbar_arrive_remote(p_barE1);
                mbar_wait(barE1, ph);
                float2 p = ypeer[w];
                tvl[w] = make_float2(__expf(2.f * (a  + p.x + bllreg)), wlreg);
                tvg[w] = make_float2(__expf(2.f * (bg + p.y + blgreg)), wgreg);
            }
        }
        __syncthreads();   // B3 (tv ready; ypeer region freed for psl)

        // ---- partials: packed f32x2 ----
        if (grp < 3) {
            ull acc0 = 0, acc1 = 0;
            #pragma unroll
            for (int dq = 0; dq < 6; dq++) {
                float2 t0 = tvg[4*dq+0], t1 = tvg[4*dq+1];
                float2 t2 = tvg[4*dq+2], t3 = tvg[4*dq+3];
                ull F1 = pkdup(t0.x), W1 = pkdup(t0.y);
                ull F2 = pkdup(t1.x), W2 = pkdup(t1.y);
                ull F3 = pkdup(t2.x), W3 = pkdup(t2.y);
                ull F4 = pkdup(t3.x), W4 = pkdup(t3.y);
                {
                    ull D1 = fma2(Epk0, F1, one2), D2 = fma2(Epk0, F2, one2);
                    ull D3 = fma2(Epk0, F3, one2), D4 = fma2(Epk0, F4, one2);
                    ull p12 = mul2(D1, D2), p34 = mul2(D3, D4);
                    ull n12 = fma2(W2, D1, mul2(W1, D2));
                    ull n34 = fma2(W4, D3, mul2(W3, D4));
                    ull num = fma2(n34, p12, mul2(n12, p34));
                    acc0 = fma2(num, rcp2(mul2(p12, p34)), acc0);
                }
                {
                    ull D1 = fma2(Epk1, F1, one2), D2 = fma2(Epk1, F2, one2);
                    ull D3 = fma2(Epk1, F3, one2), D4 = fma2(Epk1, F4, one2);
                    ull p12 = mul2(D1, D2), p34 = mul2(D3, D4);
                    ull n12 = fma2(W2, D1, mul2(W1, D2));
                    ull n34 = fma2(W4, D3, mul2(W3, D4));
                    ull num = fma2(n34, p12, mul2(n12, p34));
                    acc1 = fma2(num, rcp2(mul2(p12, p34)), acc1);
                }
            }
            float2 u0 = upk(acc0), u1 = upk(acc1);
            psg[grp * NS + sdx] = (u0.x + u0.y) + (u1.x + u1.y);
        } else if (tid < 960) {
            int idx = tid - 768;
            ull acc = 0;
            #pragma unroll
            for (int dq = 0; dq < 6; dq++) {
                float2 t0 = tvl[4*dq+0], t1 = tvl[4*dq+1];
                float2 t2 = tvl[4*dq+2], t3 = tvl[4*dq+3];
                ull F1 = pkdup(t0.x), W1 = pkdup(t0.y);
                ull F2 = pkdup(t1.x), W2 = pkdup(t1.y);
                ull F3 = pkdup(t2.x), W3 = pkdup(t2.y);
                ull F4 = pkdup(t3.x), W4 = pkdup(t3.y);
                ull D1 = fma2(Elpk, F1, one2), D2 = fma2(Elpk, F2, one2);
                ull D3 = fma2(Elpk, F3, one2), D4 = fma2(Elpk, F4, one2);
                ull p12 = mul2(D1, D2), p34 = mul2(D3, D4);
                ull n12 = fma2(W2, D1, mul2(W1, D2));
                ull n34 = fma2(W4, D3, mul2(W3, D4));
                ull num = fma2(n34, p12, mul2(n12, p34));
                acc = fma2(num, rcp2(mul2(p12, p34)), acc);
            }
            float2 u = upk(acc);
            psl[idx] = u.x + u.y;
        }
        __syncthreads();   // B4

        // ---- reduce + E2 exchange; online-softmax warp pass ----
        float myg = 0.f, myl = 0.f;
        if (tid < NS) {
            myg = psg[tid] + psg[NS + tid] + psg[2 * NS + tid];
            stc_f32(p_sgp + (unsigned)(tid * 4), myg);
            mbar_arrive_remote(p_barE2);
            mbar_wait(barE2, ph);
        } else if (tid < NS + NI) {
            int l = tid - NS;
            #pragma unroll
            for (int p = 0; p < 6; p++) myl += psl[p * NI + l];
            stc_f32(p_slp + (unsigned)(l * 4), myl);
            mbar_arrive_remote(p_barE2);
            mbar_wait(barE2, ph);
        }

        float ereg = 0.f, mwreg = 0.f;
        if (tid < NS) {
            float vreg = myg + sgp[tid] + sgb[tid];
            float m = vreg;
            #pragma unroll
            for (int off = 16; off; off >>= 1) m = fmaxf(m, __shfl_xor_sync(0xffffffffu, m, off));
            ereg = __expf(vreg - m);
            mwreg = m;
            float su = ereg;
            #pragma unroll
            for (int off = 16; off; off >>= 1) su += __shfl_xor_sync(0xffffffffu, su, off);
            if (lane == 0) { red[w] = m; red[8 + w] = su; }
        } else if (tid < NS + NI) {   // warp 8: full local softmax
            int l = tid - NS;
            float v = myl + slp[l];
            float m = v;
            #pragma unroll
            for (int off = 16; off; off >>= 1) m = fmaxf(m, __shfl_xor_sync(0xffffffffu, m, off));
            float e = __expf(v - m);
            float su = e;
            #pragma unroll
            for (int off = 16; off; off >>= 1) su += __shfl_xor_sync(0xffffffffu, su, off);
            float a = e * frcp(su);
            if (r == 1) out_la[(size_t)(t * BB + b) * NI + l] = a;
            if (t + 1 < TT) xv[l] = a * sInp[(t + 1) * DIN + l];
        }
        __syncthreads();   // B5

        // ---- combine 8 warp (m,su) pairs; normalize; write; next xv ----
        if (tid < NS) {
            float M = fmaxf(fmaxf(fmaxf(red[0], red[1]), fmaxf(red[2], red[3])),
                            fmaxf(fmaxf(red[4], red[5]), fmaxf(red[6], red[7])));
            float su = 0.f;
            #pragma unroll
            for (int j = 0; j < 8; j++) su = fmaf(red[8 + j], __expf(red[j] - M), su);
            float a = ereg * __expf(mwreg - M) * frcp(su);
            if (r == 0) out_ga[(size_t)(t * BB + b) * NS + tid] = a;
            if (t + 1 < TT) xv[NI + tid] = a * sInp[(t + 1) * DIN + NI + tid];
        }
        __syncthreads();   // B6 (xv ready for next gates)
    }

    cluster_sync_all();
}

extern "C" void kernel_launch(void* const* d_in, const int* in_sizes, int n_in,
                              void* d_out, int out_size) {
    const float* local_inputs  = (const float*)d_in[0];
    const float* global_inputs = (const float*)d_in[1];
    const float* local_states  = (const float*)d_in[2];
    const float* global_states = (const float*)d_in[3];
    const float* distmat       = (const float*)d_in[4];
    const float* la0           = (const float*)d_in[5];
    const float* ga0           = (const float*)d_in[6];
    const float* Wcl = (const float*)d_in[7];
    const float* bcl = (const float*)d_in[8];
    const float* Wll = (const float*)d_in[9];
    const float* bll = (const float*)d_in[10];
    const float* vl  = (const float*)d_in[11];
    const float* Wcg = (const float*)d_in[12];
    const float* bcg = (const float*)d_in[13];
    const float* Wlg = (const float*)d_in[14];
    const float* blg = (const float*)d_in[15];
    const float* vg  = (const float*)d_in[16];
    const float* Wih = (const float*)d_in[17];
    const float* bih = (const float*)d_in[18];
    const float* bhh = (const float*)d_in[19];
    float* out = (float*)d_out;

    cudaFuncSetAttribute(spatial_attn_kernel,
                         cudaFuncAttributeMaxDynamicSharedMemorySize, SMEM_BYTES);

    prep_kernel<<<(2 * KC * JJ + 255) / 256, 256>>>(Wih, bih, bhh);
    spatial_attn_kernel<<<2 * BB, NTHREADS, SMEM_BYTES>>>(
        local_inputs, global_inputs, local_states, global_states, distmat,
        la0, ga0, Wcl, bcl, Wll, bll, vl, Wcg, bcg, Wlg, blg, vg, out);
}